// round 12
// baseline (speedup 1.0000x reference)
#include <cuda_runtime.h>
#include <cuda_bf16.h>
#include <math.h>
#include <stdint.h>

#define NCRYST 64
#define ATOMS  32
#define NATOM  2048
#define NBR    20
#define NEDGE  40960
#define CCH    128
#define HID    256
#define NBIN   128
#define NLAYER 8
#define KH     19
#define NCTA_MLP (NEDGE/128)     // 320

typedef unsigned long long u64;
typedef unsigned int u32;

// ---------------- scratch ----------------
__device__ float g_dirn[NEDGE * 3];
__device__ float g_Y   [NEDGE * KH];
__device__ float g_rbf [NEDGE * NBIN];
__device__ float g_x   [NATOM * KH * CCH];
__device__ float g_s   [NEDGE * CCH];
__device__ float g_m   [NEDGE * CCH];
__device__ float g_hw  [NATOM];
__device__ uint4 g_w1img[8*2*4*2*1024];          // 2 MB
__device__ uint4 g_w2img[8*4*2*1024];            // 1 MB
__device__ uint4 g_aimg [NCTA_MLP*4*2*1024];     // rbf chunks 2,3 used

// ---------------- helpers ----------------
__device__ __forceinline__ u32 s2u(const void* p){ return (u32)__cvta_generic_to_shared(p); }
__device__ __forceinline__ void cpasync16(void* dst, const void* src){
    asm volatile("cp.async.cg.shared.global [%0], [%1], 16;" :: "r"(s2u(dst)), "l"(src));
}
#define CP_COMMIT asm volatile("cp.async.commit_group;" ::: "memory")
#define CP_WAIT0  asm volatile("cp.async.wait_group 0;" ::: "memory")
#define CP_WAIT1  asm volatile("cp.async.wait_group 1;" ::: "memory")

__device__ __forceinline__ void split2(float v0, float v1, u32& hi, u32& lo){
    __nv_bfloat16 h0 = __float2bfloat16_rn(v0);
    __nv_bfloat16 h1 = __float2bfloat16_rn(v1);
    float l0 = v0 - __bfloat162float(h0);
    float l1 = v1 - __bfloat162float(h1);
    __nv_bfloat162 H; H.x = h0; H.y = h1;
    __nv_bfloat162 L = __floats2bfloat162_rn(l0, l1);
    hi = *(u32*)&H; lo = *(u32*)&L;
}

__device__ __forceinline__ void mma16816(float* c, const uint4 a, const u32 b0, const u32 b1){
    asm volatile("mma.sync.aligned.m16n8k16.row.col.f32.bf16.bf16.f32 "
        "{%0,%1,%2,%3}, {%4,%5,%6,%7}, {%8,%9}, {%0,%1,%2,%3};"
        : "+f"(c[0]), "+f"(c[1]), "+f"(c[2]), "+f"(c[3])
        : "r"(a.x), "r"(a.y), "r"(a.z), "r"(a.w), "r"(b0), "r"(b1));
}

// ---------------- k_init ----------------
__global__ __launch_bounds__(512) void k_init(
        const float* __restrict__ z, const float* __restrict__ frac,
        const float* __restrict__ lengths, const float* __restrict__ angles,
        const float* __restrict__ zproj, const int* __restrict__ types,
        const float* __restrict__ emb, const int* __restrict__ ei) {
    int cb = blockIdx.x, tid = threadIdx.x;
    __shared__ float lats[9];
    __shared__ float zs[256];
    __shared__ float poss[ATOMS*3];
    __shared__ float zcs[CCH];
    __shared__ float ds[640];
    int abase = cb*ATOMS;
    int ebase = cb*640;

    if (tid == 0) {
        float a = lengths[cb*3+0], b = lengths[cb*3+1], c = lengths[cb*3+2];
        const float D2R = 0.017453292519943295f;
        float r0 = angles[cb*3+0]*D2R, r1 = angles[cb*3+1]*D2R, r2 = angles[cb*3+2]*D2R;
        float ca = cosf(r0), cbta = cosf(r1), cg = cosf(r2), sg = sinf(r2);
        float v3y = (ca - cbta*cg)/sg;
        float t = 1.0f - cbta*cbta - v3y*v3y;
        if (t < 1e-8f) t = 1e-8f;
        float v3z = sqrtf(t);
        lats[0]=a;        lats[1]=0.f;     lats[2]=0.f;
        lats[3]=b*cg;     lats[4]=b*sg;    lats[5]=0.f;
        lats[6]=c*cbta;   lats[7]=c*v3y;   lats[8]=c*v3z;
    }
    if (tid < 256) zs[tid] = z[cb*256 + tid];
    __syncthreads();
    if (tid < 96) {
        int a = tid/3, j = tid%3;
        int n = abase + a;
        poss[a*3+j] = frac[n*3+0]*lats[0+j] + frac[n*3+1]*lats[3+j] + frac[n*3+2]*lats[6+j];
    }
    if (tid < 128) {
        float acc = 0.f;
        for (int i = 0; i < 256; i++) acc += zs[i]*zproj[i*CCH + tid];
        zcs[tid] = acc;
    }
    __syncthreads();

    for (int i = tid; i < ATOMS*CCH; i += 512) {
        int a = i >> 7, c = i & 127;
        int n = abase + a;
        g_x[(size_t)(n*KH)*CCH + c] = emb[types[n]*CCH + c] + zcs[c];
    }
    for (int i4 = tid; i4 < ATOMS*18*CCH/4; i4 += 512) {
        int flat = i4*4;
        int a = flat/(18*CCH);
        int r = flat - a*(18*CCH);
        int k = 1 + (r >> 7), c = r & 127;
        *(float4*)&g_x[((size_t)(abase+a)*KH + k)*CCH + c] = make_float4(0.f,0.f,0.f,0.f);
    }

    for (int e = tid; e < 640; e += 512) {
        int s = ei[ebase + e] - abase, d = ei[NEDGE + ebase + e] - abase;
        float vx = poss[s*3+0]-poss[d*3+0];
        float vy = poss[s*3+1]-poss[d*3+1];
        float vz = poss[s*3+2]-poss[d*3+2];
        float dist = sqrtf(vx*vx + vy*vy + vz*vz) + 1e-8f;
        ds[e] = dist;
        float dx = vx/dist, dy = vy/dist, dz = vz/dist;
        int ge = ebase + e;
        g_dirn[ge*3+0]=dx; g_dirn[ge*3+1]=dy; g_dirn[ge*3+2]=dz;
        float ct = dz;
        float rho = sqrtf(dx*dx + dy*dy) + 1e-12f;
        float cph = dx/rho, sph = dy/rho;
        float P0[7]; P0[0]=1.f; P0[1]=ct;
        #pragma unroll
        for (int l=2;l<=6;l++) P0[l] = ((2*l-1)*ct*P0[l-1] - (l-1)*P0[l-2]) / l;
        float P1[7]; P1[0]=0.f; P1[1]=-rho; P1[2]=-3.f*ct*rho;
        #pragma unroll
        for (int l=3;l<=6;l++) P1[l] = ((2*l-1)*ct*P1[l-1] - l*P1[l-2]) / (l-1);
        float* Yp = &g_Y[(size_t)ge*KH];
        const float FPI = 12.566370614359172f;
        Yp[0] = 0.28209479177387814f;
        int idx = 1;
        #pragma unroll
        for (int l=1;l<=6;l++) {
            float K0 = sqrtf((2*l+1)/FPI);
            float K1 = sqrtf(2.f*(2*l+1)/(FPI*l*(l+1)));
            Yp[idx++] = K1*P1[l]*sph;
            Yp[idx++] = K0*P0[l];
            Yp[idx++] = K1*P1[l]*cph;
        }
    }
    __syncthreads();

    const float step = 8.0f/127.0f;
    const float inv  = 127.0f/8.0f;
    for (int i = tid; i < 640*NBIN; i += 512) {
        int e = i >> 7, bin = i & 127;
        float t = (ds[e] - step*(float)bin)*inv;
        g_rbf[(size_t)(ebase+e)*NBIN + bin] = expf(-0.5f*t*t);
    }
    __syncthreads();

    for (int i = tid; i < 5*2*1024; i += 512) {
        int lc  = i >> 11;
        int r   = i & 2047;
        int chl = r >> 10;
        int w   = r & 1023;
        int cta = cb*5 + lc;
        int mt = w >> 7, ktl = (w >> 5) & 3, lane = w & 31;
        int m0 = mt*16 + (lane >> 2);
        int kk = chl*64 + ktl*16 + (lane & 3)*2;
        size_t row0 = (size_t)(cta*128 + m0) * NBIN;
        size_t row1 = row0 + 8*NBIN;
        float2 p00 = *(const float2*)&g_rbf[row0 + kk];
        float2 p10 = *(const float2*)&g_rbf[row1 + kk];
        float2 p01 = *(const float2*)&g_rbf[row0 + kk + 8];
        float2 p11 = *(const float2*)&g_rbf[row1 + kk + 8];
        uint4 hi, lo;
        split2(p00.x, p00.y, hi.x, lo.x);
        split2(p10.x, p10.y, hi.y, lo.y);
        split2(p01.x, p01.y, hi.z, lo.z);
        split2(p11.x, p11.y, hi.w, lo.w);
        size_t base = ((size_t)(cta*4 + chl + 2)*2) * 1024 + w;
        g_aimg[base]        = hi;
        g_aimg[base + 1024] = lo;
    }
}

// ---------------- k_wconv ----------------
__global__ void k_wconv(const float* __restrict__ W1, const float* __restrict__ Wd,
                        const float* __restrict__ W2) {
    int t = blockIdx.x * 256 + threadIdx.x;
    if (t < 65536) {
        int l  = t >> 13;
        int r  = t & 8191;
        int nh = r >> 12;
        int ch = (r >> 10) & 3;
        int w  = r & 1023;
        int np = w >> 7, ktl = (w >> 5) & 3, lane = w & 31;
        int nE = nh*128 + np*16 + (lane >> 2);
        int nO = nE + 8;
        int k0 = ch*64 + ktl*16 + (lane & 3)*2;
        float v[8];
        #pragma unroll
        for (int q = 0; q < 4; q++) {
            int n = (q < 2) ? nE : nO;
            int kk = k0 + ((q & 1) ? 8 : 0);
            float a0, a1;
            if (kk < 128) { a0 = W1[l*32768 + kk*256 + n];       a1 = W1[l*32768 + (kk+1)*256 + n]; }
            else          { a0 = Wd[l*32768 + (kk-128)*256 + n]; a1 = Wd[l*32768 + (kk-127)*256 + n]; }
            v[q*2] = a0; v[q*2+1] = a1;
        }
        uint4 hi, lo;
        split2(v[0], v[1], hi.x, lo.x);
        split2(v[2], v[3], hi.y, lo.y);
        split2(v[4], v[5], hi.z, lo.z);
        split2(v[6], v[7], hi.w, lo.w);
        size_t base = ((size_t)((l*2 + nh)*4 + ch)*2) * 1024 + w;
        g_w1img[base]        = hi;
        g_w1img[base + 1024] = lo;
    } else if (t < 98304) {
        int u  = t - 65536;
        int l  = u >> 12;
        int ch = (u >> 10) & 3;
        int w  = u & 1023;
        int np = w >> 7, ktl = (w >> 5) & 3, lane = w & 31;
        int nE = np*16 + (lane >> 2);
        int nO = nE + 8;
        int k0 = ch*64 + ktl*16 + (lane & 3)*2;
        float v[8];
        #pragma unroll
        for (int q = 0; q < 4; q++) {
            int n = (q < 2) ? nE : nO;
            int kk = k0 + ((q & 1) ? 8 : 0);
            v[q*2]   = W2[l*32768 + kk*128 + n];
            v[q*2+1] = W2[l*32768 + (kk+1)*128 + n];
        }
        uint4 hi, lo;
        split2(v[0], v[1], hi.x, lo.x);
        split2(v[2], v[3], hi.y, lo.y);
        split2(v[4], v[5], hi.z, lo.z);
        split2(v[6], v[7], hi.w, lo.w);
        size_t base = ((size_t)(l*4 + ch)*2) * 1024 + w;
        g_w2img[base]        = hi;
        g_w2img[base + 1024] = lo;
    }
}

// ---------------- k_s ----------------
#define XS_STRIDE 20
#define XS_F (ATOMS*KH*XS_STRIDE)
#define YS_F (640*KH)
__global__ __launch_bounds__(256, 2) void k_s(const int* __restrict__ ei) {
    int cq = blockIdx.x;
    int cb = blockIdx.y;
    int tid = threadIdx.x;
    extern __shared__ float sm[];
    float* xs  = sm;
    float* Ys  = sm + XS_F;
    int*  srcs = (int*)(Ys + YS_F);
    int abase = cb*ATOMS;
    int c0 = cq*16;
    for (int i = tid; i < ATOMS*KH*16; i += 256) {
        int a = i/(KH*16); int r = i - a*(KH*16); int k = r >> 4; int c = r & 15;
        xs[(a*KH + k)*XS_STRIDE + c] = g_x[((size_t)(abase+a)*KH + k)*CCH + c0 + c];
    }
    int ebase = cb*640;
    for (int i = tid; i < YS_F; i += 256) Ys[i] = g_Y[(size_t)ebase*KH + i];
    for (int i = tid; i < 640; i += 256) srcs[i] = ei[ebase + i] - abase;
    __syncthreads();
    int cg = tid & 3, er = tid >> 2;
    #pragma unroll 2
    for (int j = 0; j < 10; j++) {
        int e = j*64 + er;
        int sl = srcs[e];
        const float* xr = &xs[sl*(KH*XS_STRIDE) + cg*4];
        const float* yr = &Ys[e*KH];
        float4 acc = make_float4(0.f, 0.f, 0.f, 0.f);
        #pragma unroll
        for (int k = 0; k < KH; k++) {
            float y = yr[k];
            float4 xv = *(const float4*)&xr[k*XS_STRIDE];
            acc.x = fmaf(y, xv.x, acc.x);
            acc.y = fmaf(y, xv.y, acc.y);
            acc.z = fmaf(y, xv.z, acc.z);
            acc.w = fmaf(y, xv.w, acc.w);
        }
        *(float4*)&g_s[(size_t)(ebase+e)*CCH + c0 + cg*4] = acc;
    }
}

// ---------------- k_mlp: 1024 thr / 32 warps (8m x 4n), double-buffered bf16 3-pass ----------------
#define SM_MLP   196608

__global__ __launch_bounds__(1024, 1) void k_mlp(int layer) {
    extern __shared__ char smem[];
    int tid = threadIdx.x;
    int wid = tid >> 5, lane = tid & 31;
    int mw = wid & 7, nw = wid >> 3;       // 8 m-warps x 4 n-warps
    int cta = blockIdx.x;
    int e0 = cta * 128;
    int g  = lane >> 2;
    int tg = lane & 3;

    uint4* Bb0 = (uint4*)smem;             // 64 KB
    uint4* Bb1 = (uint4*)(smem + 65536);
    uint4* sA0 = (uint4*)(smem + 131072);  // 32 KB
    uint4* sA1 = (uint4*)(smem + 163840);  // 32 KB
    uint4* hs4 = (uint4*)smem;
    u32*   hsw = (u32*)smem;

    int nh     = nw >> 1;
    int npbase = (nw & 1) * 4;

    // ---- hoist s LDGs ----
    float2 sv[2][4];
    {
        int w = tid;
        int mt = w >> 7, ktl = (w >> 5) & 3, ln = w & 31;
        int m0 = mt*16 + (ln >> 2);
        int kkb = ktl*16 + (ln & 3)*2;
        size_t row0 = (size_t)(e0 + m0)*CCH;
        size_t row1 = row0 + 8*CCH;
        #pragma unroll
        for (int ch = 0; ch < 2; ch++) {
            int kk = ch*64 + kkb;
            sv[ch][0] = *(const float2*)&g_s[row0 + kk];
            sv[ch][1] = *(const float2*)&g_s[row1 + kk];
            sv[ch][2] = *(const float2*)&g_s[row0 + kk + 8];
            sv[ch][3] = *(const float2*)&g_s[row1 + kk + 8];
        }
    }

    // ---- fill B(0) ----
    {
        const uint4* b0 = g_w1img + ((size_t)((layer*2 + 0)*4 + 0)*2) * 1024;
        const uint4* b1 = g_w1img + ((size_t)((layer*2 + 1)*4 + 0)*2) * 1024;
        #pragma unroll
        for (int i = 0; i < 2; i++) cpasync16(&Bb0[tid + i*1024],        &b0[tid + i*1024]);
        #pragma unroll
        for (int i = 0; i < 2; i++) cpasync16(&Bb0[2048 + tid + i*1024], &b1[tid + i*1024]);
        CP_COMMIT;   // g1
    }
    // ---- convert s regs -> sA0 (ch0), sA1 (ch1) ----
    #pragma unroll
    for (int ch = 0; ch < 2; ch++) {
        uint4* dst = ch ? sA1 : sA0;
        uint4 hi, lo;
        split2(sv[ch][0].x, sv[ch][0].y, hi.x, lo.x);
        split2(sv[ch][1].x, sv[ch][1].y, hi.y, lo.y);
        split2(sv[ch][2].x, sv[ch][2].y, hi.z, lo.z);
        split2(sv[ch][3].x, sv[ch][3].y, hi.w, lo.w);
        dst[tid]        = hi;
        dst[1024 + tid] = lo;
    }
    // ---- fill B(1) ----
    {
        const uint4* b0 = g_w1img + ((size_t)((layer*2 + 0)*4 + 1)*2) * 1024;
        const uint4* b1 = g_w1img + ((size_t)((layer*2 + 1)*4 + 1)*2) * 1024;
        #pragma unroll
        for (int i = 0; i < 2; i++) cpasync16(&Bb1[tid + i*1024],        &b0[tid + i*1024]);
        #pragma unroll
        for (int i = 0; i < 2; i++) cpasync16(&Bb1[2048 + tid + i*1024], &b1[tid + i*1024]);
        CP_COMMIT;   // g2
    }

    float acc1[8][4];
    #pragma unroll
    for (int j = 0; j < 8; j++)
        #pragma unroll
        for (int q = 0; q < 4; q++) acc1[j][q] = 0.f;

    #define G1_COMPUTE(Acur, Bcur)                                               \
    {                                                                            \
        _Pragma("unroll")                                                        \
        for (int kt = 0; kt < 4; kt++) {                                         \
            int aidx = (mw*4 + kt)*32 + lane;                                    \
            uint4 aH = (Acur)[aidx];                                             \
            uint4 aL = (Acur)[1024 + aidx];                                      \
            _Pragma("unroll")                                                    \
            for (int j = 0; j < 4; j++) {                                        \
                int idx = nh*2048 + ((npbase + j)*4 + kt)*32 + lane;             \
                uint4 bH = (Bcur)[idx];                                          \
                uint4 bL = (Bcur)[1024 + idx];                                   \
                mma16816(acc1[2*j],   aH, bH.x, bH.y);                           \
                mma16816(acc1[2*j+1], aH, bH.z, bH.w);                           \
                mma16816(acc1[2*j],   aH, bL.x, bL.y);                           \
                mma16816(acc1[2*j+1], aH, bL.z, bL.w);                           \
                mma16816(acc1[2*j],   aL, bH.x, bH.y);                           \
                mma16816(acc1[2*j+1], aL, bH.z, bH.w);                           \
            }                                                                    \
        }                                                                        \
    }

    #define FILL_B1(ch, Bp)                                                          \
    {                                                                                \
        const uint4* b0 = g_w1img + ((size_t)((layer*2 + 0)*4 + (ch))*2) * 1024;     \
        const uint4* b1 = g_w1img + ((size_t)((layer*2 + 1)*4 + (ch))*2) * 1024;     \
        _Pragma("unroll")                                                            \
        for (int i = 0; i < 2; i++) cpasync16(&(Bp)[tid + i*1024],        &b0[tid + i*1024]); \
        _Pragma("unroll")                                                            \
        for (int i = 0; i < 2; i++) cpasync16(&(Bp)[2048 + tid + i*1024], &b1[tid + i*1024]); \
    }
    #define FILL_A(ch, Ap)                                                           \
    {                                                                                \
        const uint4* gA = g_aimg + ((size_t)(cta*4 + (ch))*2) * 1024;                \
        _Pragma("unroll")                                                            \
        for (int i = 0; i < 2; i++) cpasync16(&(Ap)[tid + i*1024], &gA[tid + i*1024]); \
    }

    CP_WAIT1; __syncthreads();          // B(0) ready
    G1_COMPUTE(sA0, Bb0);               // ch 0
    __syncthreads();
    FILL_A(2, sA0); FILL_B1(2, Bb0); CP_COMMIT;   // g3
    CP_WAIT1; __syncthreads();          // B(1) ready
    G1_COMPUTE(sA1, Bb1);               // ch 1
    __syncthreads();
    FILL_A(3, sA1); FILL_B1(3, Bb1); CP_COMMIT;   // g4
    CP_WAIT1; __syncthreads();          // A(2)/B(2) ready
    G1_COMPUTE(sA0, Bb0);               // ch 2
    __syncthreads();
    {   // prefetch GEMM2 B(0) into sA0 (free after ch2)
        const uint4* gB = g_w2img + ((size_t)(layer*4 + 0)*2) * 1024;
        #pragma unroll
        for (int i = 0; i < 2; i++) cpasync16(&sA0[tid + i*1024], &gB[tid + i*1024]);
        CP_COMMIT;   // g5
    }
    CP_WAIT1; __syncthreads();          // A(3)/B(3) ready
    G1_COMPUTE(sA1, Bb1);               // ch 3
    __syncthreads();                    // Bb region free -> h storage

    // ---- epilogue 1: silu + split -> h fragments ----
    #pragma unroll
    for (int nt = 0; nt < 8; nt++) {
        float c0 = acc1[nt][0], c1 = acc1[nt][1];
        float c2 = acc1[nt][2], c3 = acc1[nt][3];
        c0 = c0 / (1.f + __expf(-c0));
        c1 = c1 / (1.f + __expf(-c1));
        c2 = c2 / (1.f + __expf(-c2));
        c3 = c3 / (1.f + __expf(-c3));
        int C = nw*64 + (nt >> 1)*16 + (nt & 1)*8 + tg*2;
        u32 hi01, lo01, hi23, lo23;
        split2(c0, c1, hi01, lo01);
        split2(c2, c3, hi23, lo23);
        int ktp  = C >> 4;
        int khal = (C >> 3) & 1;
        int lanep = g*4 + tg;
        u32 base = (((u32)(mw*16 + ktp)*32 + lanep) << 2);
        hsw[base + 2*khal]             = hi01;
        hsw[base + 2*khal + 1]         = hi23;
        hsw[16384 + base + 2*khal]     = lo01;
        hsw[16384 + base + 2*khal + 1] = lo23;
    }
    CP_WAIT0;
    __syncthreads();

    // ===================== GEMM2 =====================
    float acc2[4][4];
    #pragma unroll
    for (int j = 0; j < 4; j++)
        #pragma unroll
        for (int q = 0; q < 4; q++) acc2[j][q] = 0.f;

    uint4* B2[2] = { sA0, sA1 };
    for (int ch = 0; ch < 4; ch++) {
        if (ch < 3) {
            const uint4* gB = g_w2img + ((size_t)(layer*4 + ch + 1)*2) * 1024;
            uint4* Bnx = B2[(ch+1) & 1];
            #pragma unroll
            for (int i = 0; i < 2; i++) cpasync16(&Bnx[tid + i*1024], &gB[tid + i*1024]);
            CP_COMMIT;
        }
        const uint4* Bcur = B2[ch & 1];
        #pragma unroll
        for (int kt = 0; kt < 4; kt++) {
            int ktg = ch*4 + kt;
            int aidx = (mw*16 + ktg)*32 + lane;
            uint4 aH = hs4[aidx];
            uint4 aL = hs4[4096 + aidx];
            #pragma unroll
            for (int j = 0; j < 2; j++) {
                int idx = ((nw*2 + j)*4 + kt)*32 + lane;
                uint4 bH = Bcur[idx];
                uint4 bL = Bcur[1024 + idx];
                mma16816(acc2[2*j],   aH, bH.x, bH.y);
                mma16816(acc2[2*j+1], aH, bH.z, bH.w);
                mma16816(acc2[2*j],   aH, bL.x, bL.y);
                mma16816(acc2[2*j+1], aH, bL.z, bL.w);
                mma16816(acc2[2*j],   aL, bH.x, bH.y);
                mma16816(acc2[2*j+1], aL, bH.z, bH.w);
            }
        }
        if (ch < 3) { CP_WAIT0; __syncthreads(); }
    }

    #pragma unroll
    for (int nt = 0; nt < 4; nt++) {
        int R = mw*16 + g;
        int C = nw*32 + (nt >> 1)*16 + (nt & 1)*8 + tg*2;
        float2 v0 = make_float2(acc2[nt][0], acc2[nt][1]);
        float2 v1 = make_float2(acc2[nt][2], acc2[nt][3]);
        *(float2*)&g_m[(size_t)(e0 + R)*CCH + C]     = v0;
        *(float2*)&g_m[(size_t)(e0 + R + 8)*CCH + C] = v1;
    }
}

// ---------------- k_agg ----------------
__global__ void k_agg() {
    int n = blockIdx.x, tid = threadIdx.x;
    __shared__ float mS[NBR*CCH];
    __shared__ float yS[NBR*KH];
    int eb = n*NBR;
    for (int i = tid; i < NBR*CCH; i += 128) mS[i] = g_m[(size_t)eb*CCH + i];
    for (int i = tid; i < NBR*KH;  i += 128) yS[i] = g_Y[(size_t)eb*KH + i];
    __syncthreads();
    int c = tid;
    float acc[KH];
    #pragma unroll
    for (int k = 0; k < KH; k++) acc[k] = 0.f;
    #pragma unroll
    for (int e = 0; e < NBR; e++) {
        float mv = mS[e*CCH + c];
        #pragma unroll
        for (int k = 0; k < KH; k++) acc[k] = fmaf(yS[e*KH + k], mv, acc[k]);
    }
    #pragma unroll
    for (int k = 0; k < KH; k++) g_x[((size_t)n*KH + k)*CCH + c] += acc[k]*0.05f;
}

// ---------------- k_hw ----------------
__global__ void k_hw(const float* __restrict__ wf) {
    int n = blockIdx.x, lane = threadIdx.x;
    float v = 0.f;
    for (int c = lane; c < CCH; c += 32) v += g_x[(size_t)n*(KH*CCH) + c]*wf[c];
    #pragma unroll
    for (int off = 16; off; off >>= 1) v += __shfl_xor_sync(0xffffffffu, v, off);
    if (lane == 0) g_hw[n] = v;
}

// ---------------- k_out ----------------
__global__ void k_out(const float* __restrict__ Wa, const float* __restrict__ ba,
                      const int* __restrict__ ei, float* __restrict__ out) {
    int n = blockIdx.x, tid = threadIdx.x;
    __shared__ float hs[CCH];
    hs[tid] = g_x[(size_t)n*(KH*CCH) + tid];
    __syncthreads();
    if (tid < 100) {
        float acc = ba[tid];
        for (int c = 0; c < CCH; c++) acc = fmaf(hs[c], Wa[c*100 + tid], acc);
        out[NATOM*3 + n*100 + tid] = acc;
    } else if (tid < 103) {
        int j = tid - 100;
        float hwn = g_hw[n];
        float acc = 0.f;
        for (int e = 0; e < NBR; e++) {
            int ge = n*NBR + e;
            acc = fmaf(g_hw[ei[ge]] - hwn, g_dirn[ge*3 + j], acc);
        }
        out[n*3 + j] = acc;
    }
}

// ---------------- launch ----------------
static const int SMEM_S = (XS_F + YS_F)*4 + 640*4;

extern "C" void kernel_launch(void* const* d_in, const int* in_sizes, int n_in,
                              void* d_out, int out_size) {
    const float* z       = (const float*)d_in[0];
    const float* frac    = (const float*)d_in[1];
    const int*   types   = (const int*)  d_in[2];
    const float* lengths = (const float*)d_in[4];
    const float* angles  = (const float*)d_in[5];
    const int*   ei      = (const int*)  d_in[7];
    const float* emb     = (const float*)d_in[8];
    const float* zproj   = (const float*)d_in[9];
    const float* Wd      = (const float*)d_in[10];
    const float* W1      = (const float*)d_in[11];
    const float* W2      = (const float*)d_in[12];
    const float* Wa      = (const float*)d_in[13];
    const float* ba      = (const float*)d_in[14];
    const float* wf      = (const float*)d_in[15];
    float* out = (float*)d_out;

    cudaFuncSetAttribute(k_s,   cudaFuncAttributeMaxDynamicSharedMemorySize, SMEM_S);
    cudaFuncSetAttribute(k_mlp, cudaFuncAttributeMaxDynamicSharedMemorySize, SM_MLP);

    k_init <<<NCRYST, 512>>>(z, frac, lengths, angles, zproj, types, emb, ei);
    k_wconv<<<384, 256>>>(W1, Wd, W2);
    for (int l = 0; l < NLAYER; l++) {
        k_s  <<<dim3(8, NCRYST), 256, SMEM_S>>>(ei);
        k_mlp<<<NCTA_MLP, 1024, SM_MLP>>>(l);
        k_agg<<<NATOM, 128>>>();
    }
    k_hw <<<NATOM, 32>>>(wf);
    k_out<<<NATOM, 128>>>(Wa, ba, ei, out);
}

// round 13
// speedup vs baseline: 1.0602x; 1.0602x over previous
#include <cuda_runtime.h>
#include <cuda_bf16.h>
#include <math.h>
#include <stdint.h>

#define NCRYST 64
#define ATOMS  32
#define NATOM  2048
#define NBR    20
#define NEDGE  40960
#define CCH    128
#define HID    256
#define NBIN   128
#define NLAYER 8
#define KH     19
#define NCTA_MLP (NEDGE/128)     // 320

typedef unsigned long long u64;
typedef unsigned int u32;

// ---------------- scratch ----------------
__device__ float g_dirn[NEDGE * 3];
__device__ float g_Y   [NEDGE * KH];
__device__ float g_rbf [NEDGE * NBIN];
__device__ float g_x   [NATOM * KH * CCH];
__device__ float g_s   [NEDGE * CCH];
__device__ float g_hw  [NATOM];
__device__ uint4 g_w1img[8*2*4*2*1024];          // 2 MB
__device__ uint4 g_w2img[8*4*2*1024];            // 1 MB
__device__ uint4 g_aimg [NCTA_MLP*4*2*1024];     // rbf chunks 2,3 used

// ---------------- helpers ----------------
__device__ __forceinline__ u32 s2u(const void* p){ return (u32)__cvta_generic_to_shared(p); }
__device__ __forceinline__ void cpasync16(void* dst, const void* src){
    asm volatile("cp.async.cg.shared.global [%0], [%1], 16;" :: "r"(s2u(dst)), "l"(src));
}
#define CP_COMMIT asm volatile("cp.async.commit_group;" ::: "memory")
#define CP_WAIT0  asm volatile("cp.async.wait_group 0;" ::: "memory")
#define CP_WAIT1  asm volatile("cp.async.wait_group 1;" ::: "memory")

__device__ __forceinline__ void split2(float v0, float v1, u32& hi, u32& lo){
    __nv_bfloat16 h0 = __float2bfloat16_rn(v0);
    __nv_bfloat16 h1 = __float2bfloat16_rn(v1);
    float l0 = v0 - __bfloat162float(h0);
    float l1 = v1 - __bfloat162float(h1);
    __nv_bfloat162 H; H.x = h0; H.y = h1;
    __nv_bfloat162 L = __floats2bfloat162_rn(l0, l1);
    hi = *(u32*)&H; lo = *(u32*)&L;
}

__device__ __forceinline__ void mma16816(float* c, const uint4 a, const u32 b0, const u32 b1){
    asm volatile("mma.sync.aligned.m16n8k16.row.col.f32.bf16.bf16.f32 "
        "{%0,%1,%2,%3}, {%4,%5,%6,%7}, {%8,%9}, {%0,%1,%2,%3};"
        : "+f"(c[0]), "+f"(c[1]), "+f"(c[2]), "+f"(c[3])
        : "r"(a.x), "r"(a.y), "r"(a.z), "r"(a.w), "r"(b0), "r"(b1));
}

// ---------------- k_init ----------------
__global__ __launch_bounds__(512) void k_init(
        const float* __restrict__ z, const float* __restrict__ frac,
        const float* __restrict__ lengths, const float* __restrict__ angles,
        const float* __restrict__ zproj, const int* __restrict__ types,
        const float* __restrict__ emb, const int* __restrict__ ei) {
    int cb = blockIdx.x, tid = threadIdx.x;
    __shared__ float lats[9];
    __shared__ float zs[256];
    __shared__ float poss[ATOMS*3];
    __shared__ float zcs[CCH];
    __shared__ float ds[640];
    int abase = cb*ATOMS;
    int ebase = cb*640;

    if (tid == 0) {
        float a = lengths[cb*3+0], b = lengths[cb*3+1], c = lengths[cb*3+2];
        const float D2R = 0.017453292519943295f;
        float r0 = angles[cb*3+0]*D2R, r1 = angles[cb*3+1]*D2R, r2 = angles[cb*3+2]*D2R;
        float ca = cosf(r0), cbta = cosf(r1), cg = cosf(r2), sg = sinf(r2);
        float v3y = (ca - cbta*cg)/sg;
        float t = 1.0f - cbta*cbta - v3y*v3y;
        if (t < 1e-8f) t = 1e-8f;
        float v3z = sqrtf(t);
        lats[0]=a;        lats[1]=0.f;     lats[2]=0.f;
        lats[3]=b*cg;     lats[4]=b*sg;    lats[5]=0.f;
        lats[6]=c*cbta;   lats[7]=c*v3y;   lats[8]=c*v3z;
    }
    if (tid < 256) zs[tid] = z[cb*256 + tid];
    __syncthreads();
    if (tid < 96) {
        int a = tid/3, j = tid%3;
        int n = abase + a;
        poss[a*3+j] = frac[n*3+0]*lats[0+j] + frac[n*3+1]*lats[3+j] + frac[n*3+2]*lats[6+j];
    }
    if (tid < 128) {
        float acc = 0.f;
        for (int i = 0; i < 256; i++) acc += zs[i]*zproj[i*CCH + tid];
        zcs[tid] = acc;
    }
    __syncthreads();

    for (int i = tid; i < ATOMS*CCH; i += 512) {
        int a = i >> 7, c = i & 127;
        int n = abase + a;
        g_x[(size_t)(n*KH)*CCH + c] = emb[types[n]*CCH + c] + zcs[c];
    }
    for (int i4 = tid; i4 < ATOMS*18*CCH/4; i4 += 512) {
        int flat = i4*4;
        int a = flat/(18*CCH);
        int r = flat - a*(18*CCH);
        int k = 1 + (r >> 7), c = r & 127;
        *(float4*)&g_x[((size_t)(abase+a)*KH + k)*CCH + c] = make_float4(0.f,0.f,0.f,0.f);
    }

    for (int e = tid; e < 640; e += 512) {
        int s = ei[ebase + e] - abase, d = ei[NEDGE + ebase + e] - abase;
        float vx = poss[s*3+0]-poss[d*3+0];
        float vy = poss[s*3+1]-poss[d*3+1];
        float vz = poss[s*3+2]-poss[d*3+2];
        float dist = sqrtf(vx*vx + vy*vy + vz*vz) + 1e-8f;
        ds[e] = dist;
        float dx = vx/dist, dy = vy/dist, dz = vz/dist;
        int ge = ebase + e;
        g_dirn[ge*3+0]=dx; g_dirn[ge*3+1]=dy; g_dirn[ge*3+2]=dz;
        float ct = dz;
        float rho = sqrtf(dx*dx + dy*dy) + 1e-12f;
        float cph = dx/rho, sph = dy/rho;
        float P0[7]; P0[0]=1.f; P0[1]=ct;
        #pragma unroll
        for (int l=2;l<=6;l++) P0[l] = ((2*l-1)*ct*P0[l-1] - (l-1)*P0[l-2]) / l;
        float P1[7]; P1[0]=0.f; P1[1]=-rho; P1[2]=-3.f*ct*rho;
        #pragma unroll
        for (int l=3;l<=6;l++) P1[l] = ((2*l-1)*ct*P1[l-1] - l*P1[l-2]) / (l-1);
        float* Yp = &g_Y[(size_t)ge*KH];
        const float FPI = 12.566370614359172f;
        Yp[0] = 0.28209479177387814f;
        int idx = 1;
        #pragma unroll
        for (int l=1;l<=6;l++) {
            float K0 = sqrtf((2*l+1)/FPI);
            float K1 = sqrtf(2.f*(2*l+1)/(FPI*l*(l+1)));
            Yp[idx++] = K1*P1[l]*sph;
            Yp[idx++] = K0*P0[l];
            Yp[idx++] = K1*P1[l]*cph;
        }
    }
    __syncthreads();

    const float step = 8.0f/127.0f;
    const float inv  = 127.0f/8.0f;
    for (int i = tid; i < 640*NBIN; i += 512) {
        int e = i >> 7, bin = i & 127;
        float t = (ds[e] - step*(float)bin)*inv;
        g_rbf[(size_t)(ebase+e)*NBIN + bin] = expf(-0.5f*t*t);
    }
    __syncthreads();

    for (int i = tid; i < 5*2*1024; i += 512) {
        int lc  = i >> 11;
        int r   = i & 2047;
        int chl = r >> 10;
        int w   = r & 1023;
        int cta = cb*5 + lc;
        int mt = w >> 7, ktl = (w >> 5) & 3, lane = w & 31;
        int m0 = mt*16 + (lane >> 2);
        int kk = chl*64 + ktl*16 + (lane & 3)*2;
        size_t row0 = (size_t)(cta*128 + m0) * NBIN;
        size_t row1 = row0 + 8*NBIN;
        float2 p00 = *(const float2*)&g_rbf[row0 + kk];
        float2 p10 = *(const float2*)&g_rbf[row1 + kk];
        float2 p01 = *(const float2*)&g_rbf[row0 + kk + 8];
        float2 p11 = *(const float2*)&g_rbf[row1 + kk + 8];
        uint4 hi, lo;
        split2(p00.x, p00.y, hi.x, lo.x);
        split2(p10.x, p10.y, hi.y, lo.y);
        split2(p01.x, p01.y, hi.z, lo.z);
        split2(p11.x, p11.y, hi.w, lo.w);
        size_t base = ((size_t)(cta*4 + chl + 2)*2) * 1024 + w;
        g_aimg[base]        = hi;
        g_aimg[base + 1024] = lo;
    }
}

// ---------------- k_wconv ----------------
__global__ void k_wconv(const float* __restrict__ W1, const float* __restrict__ Wd,
                        const float* __restrict__ W2) {
    int t = blockIdx.x * 256 + threadIdx.x;
    if (t < 65536) {
        int l  = t >> 13;
        int r  = t & 8191;
        int nh = r >> 12;
        int ch = (r >> 10) & 3;
        int w  = r & 1023;
        int np = w >> 7, ktl = (w >> 5) & 3, lane = w & 31;
        int nE = nh*128 + np*16 + (lane >> 2);
        int nO = nE + 8;
        int k0 = ch*64 + ktl*16 + (lane & 3)*2;
        float v[8];
        #pragma unroll
        for (int q = 0; q < 4; q++) {
            int n = (q < 2) ? nE : nO;
            int kk = k0 + ((q & 1) ? 8 : 0);
            float a0, a1;
            if (kk < 128) { a0 = W1[l*32768 + kk*256 + n];       a1 = W1[l*32768 + (kk+1)*256 + n]; }
            else          { a0 = Wd[l*32768 + (kk-128)*256 + n]; a1 = Wd[l*32768 + (kk-127)*256 + n]; }
            v[q*2] = a0; v[q*2+1] = a1;
        }
        uint4 hi, lo;
        split2(v[0], v[1], hi.x, lo.x);
        split2(v[2], v[3], hi.y, lo.y);
        split2(v[4], v[5], hi.z, lo.z);
        split2(v[6], v[7], hi.w, lo.w);
        size_t base = ((size_t)((l*2 + nh)*4 + ch)*2) * 1024 + w;
        g_w1img[base]        = hi;
        g_w1img[base + 1024] = lo;
    } else if (t < 98304) {
        int u  = t - 65536;
        int l  = u >> 12;
        int ch = (u >> 10) & 3;
        int w  = u & 1023;
        int np = w >> 7, ktl = (w >> 5) & 3, lane = w & 31;
        int nE = np*16 + (lane >> 2);
        int nO = nE + 8;
        int k0 = ch*64 + ktl*16 + (lane & 3)*2;
        float v[8];
        #pragma unroll
        for (int q = 0; q < 4; q++) {
            int n = (q < 2) ? nE : nO;
            int kk = k0 + ((q & 1) ? 8 : 0);
            v[q*2]   = W2[l*32768 + kk*128 + n];
            v[q*2+1] = W2[l*32768 + (kk+1)*128 + n];
        }
        uint4 hi, lo;
        split2(v[0], v[1], hi.x, lo.x);
        split2(v[2], v[3], hi.y, lo.y);
        split2(v[4], v[5], hi.z, lo.z);
        split2(v[6], v[7], hi.w, lo.w);
        size_t base = ((size_t)(l*4 + ch)*2) * 1024 + w;
        g_w2img[base]        = hi;
        g_w2img[base + 1024] = lo;
    }
}

// ---------------- k_s ----------------
#define XS_STRIDE 20
#define XS_F (ATOMS*KH*XS_STRIDE)
#define YS_F (640*KH)
__global__ __launch_bounds__(256, 2) void k_s(const int* __restrict__ ei) {
    int cq = blockIdx.x;
    int cb = blockIdx.y;
    int tid = threadIdx.x;
    extern __shared__ float sm[];
    float* xs  = sm;
    float* Ys  = sm + XS_F;
    int*  srcs = (int*)(Ys + YS_F);
    int abase = cb*ATOMS;
    int c0 = cq*16;
    for (int i = tid; i < ATOMS*KH*16; i += 256) {
        int a = i/(KH*16); int r = i - a*(KH*16); int k = r >> 4; int c = r & 15;
        xs[(a*KH + k)*XS_STRIDE + c] = g_x[((size_t)(abase+a)*KH + k)*CCH + c0 + c];
    }
    int ebase = cb*640;
    for (int i = tid; i < YS_F; i += 256) Ys[i] = g_Y[(size_t)ebase*KH + i];
    for (int i = tid; i < 640; i += 256) srcs[i] = ei[ebase + i] - abase;
    __syncthreads();
    int cg = tid & 3, er = tid >> 2;
    #pragma unroll 2
    for (int j = 0; j < 10; j++) {
        int e = j*64 + er;
        int sl = srcs[e];
        const float* xr = &xs[sl*(KH*XS_STRIDE) + cg*4];
        const float* yr = &Ys[e*KH];
        float4 acc = make_float4(0.f, 0.f, 0.f, 0.f);
        #pragma unroll
        for (int k = 0; k < KH; k++) {
            float y = yr[k];
            float4 xv = *(const float4*)&xr[k*XS_STRIDE];
            acc.x = fmaf(y, xv.x, acc.x);
            acc.y = fmaf(y, xv.y, acc.y);
            acc.z = fmaf(y, xv.z, acc.z);
            acc.w = fmaf(y, xv.w, acc.w);
        }
        *(float4*)&g_s[(size_t)(ebase+e)*CCH + c0 + cg*4] = acc;
    }
}

// ---------------- k_mlp: 1024 thr, Wm4 x Wn8 tiling, fused aggregation ----------------
#define SM_MLP   196608

__global__ __launch_bounds__(1024, 1) void k_mlp(int layer) {
    extern __shared__ char smem[];
    int tid = threadIdx.x;
    int wid = tid >> 5, lane = tid & 31;
    int mw = wid & 3, nw = wid >> 2;       // 4 m-warps x 8 n-warps
    int cta = blockIdx.x;
    int e0 = cta * 128;
    int g  = lane >> 2;
    int tg = lane & 3;

    uint4* Bb0 = (uint4*)smem;             // 64 KB
    uint4* Bb1 = (uint4*)(smem + 65536);
    uint4* sA0 = (uint4*)(smem + 131072);  // 32 KB
    uint4* sA1 = (uint4*)(smem + 163840);  // 32 KB
    uint4* hs4 = (uint4*)smem;
    u32*   hsw = (u32*)smem;

    int nh  = nw >> 2;          // 0..1 (n-half of 256)
    int np2 = (nw & 3) * 2;     // np base (2 n16-pairs per warp)

    // ---- hoist s LDGs ----
    float2 sv[2][4];
    {
        int w = tid;
        int mt = w >> 7, ktl = (w >> 5) & 3, ln = w & 31;
        int m0 = mt*16 + (ln >> 2);
        int kkb = ktl*16 + (ln & 3)*2;
        size_t row0 = (size_t)(e0 + m0)*CCH;
        size_t row1 = row0 + 8*CCH;
        #pragma unroll
        for (int ch = 0; ch < 2; ch++) {
            int kk = ch*64 + kkb;
            sv[ch][0] = *(const float2*)&g_s[row0 + kk];
            sv[ch][1] = *(const float2*)&g_s[row1 + kk];
            sv[ch][2] = *(const float2*)&g_s[row0 + kk + 8];
            sv[ch][3] = *(const float2*)&g_s[row1 + kk + 8];
        }
    }

    // ---- fill B(0) ----
    {
        const uint4* b0 = g_w1img + ((size_t)((layer*2 + 0)*4 + 0)*2) * 1024;
        const uint4* b1 = g_w1img + ((size_t)((layer*2 + 1)*4 + 0)*2) * 1024;
        #pragma unroll
        for (int i = 0; i < 2; i++) cpasync16(&Bb0[tid + i*1024],        &b0[tid + i*1024]);
        #pragma unroll
        for (int i = 0; i < 2; i++) cpasync16(&Bb0[2048 + tid + i*1024], &b1[tid + i*1024]);
        CP_COMMIT;   // g1
    }
    // ---- convert s regs -> sA0 (ch0), sA1 (ch1) ----
    #pragma unroll
    for (int ch = 0; ch < 2; ch++) {
        uint4* dst = ch ? sA1 : sA0;
        uint4 hi, lo;
        split2(sv[ch][0].x, sv[ch][0].y, hi.x, lo.x);
        split2(sv[ch][1].x, sv[ch][1].y, hi.y, lo.y);
        split2(sv[ch][2].x, sv[ch][2].y, hi.z, lo.z);
        split2(sv[ch][3].x, sv[ch][3].y, hi.w, lo.w);
        dst[tid]        = hi;
        dst[1024 + tid] = lo;
    }
    // ---- fill B(1) ----
    {
        const uint4* b0 = g_w1img + ((size_t)((layer*2 + 0)*4 + 1)*2) * 1024;
        const uint4* b1 = g_w1img + ((size_t)((layer*2 + 1)*4 + 1)*2) * 1024;
        #pragma unroll
        for (int i = 0; i < 2; i++) cpasync16(&Bb1[tid + i*1024],        &b0[tid + i*1024]);
        #pragma unroll
        for (int i = 0; i < 2; i++) cpasync16(&Bb1[2048 + tid + i*1024], &b1[tid + i*1024]);
        CP_COMMIT;   // g2
    }

    float acc1[2][4][4];
    #pragma unroll
    for (int s = 0; s < 2; s++)
        #pragma unroll
        for (int j = 0; j < 4; j++)
            #pragma unroll
            for (int q = 0; q < 4; q++) acc1[s][j][q] = 0.f;

    #define G1_COMPUTE(Acur, Bcur)                                               \
    {                                                                            \
        _Pragma("unroll")                                                        \
        for (int kt = 0; kt < 4; kt++) {                                         \
            uint4 aH[2], aL[2];                                                  \
            _Pragma("unroll")                                                    \
            for (int s = 0; s < 2; s++) {                                        \
                int aidx = ((mw*2 + s)*4 + kt)*32 + lane;                        \
                aH[s] = (Acur)[aidx];                                            \
                aL[s] = (Acur)[1024 + aidx];                                     \
            }                                                                    \
            _Pragma("unroll")                                                    \
            for (int j = 0; j < 2; j++) {                                        \
                int idx = nh*2048 + ((np2 + j)*4 + kt)*32 + lane;                \
                uint4 bH = (Bcur)[idx];                                          \
                uint4 bL = (Bcur)[1024 + idx];                                   \
                _Pragma("unroll")                                                \
                for (int s = 0; s < 2; s++) {                                    \
                    mma16816(acc1[s][2*j],   aH[s], bH.x, bH.y);                 \
                    mma16816(acc1[s][2*j+1], aH[s], bH.z, bH.w);                 \
                    mma16816(acc1[s][2*j],   aH[s], bL.x, bL.y);                 \
                    mma16816(acc1[s][2*j+1], aH[s], bL.z, bL.w);                 \
                    mma16816(acc1[s][2*j],   aL[s], bH.x, bH.y);                 \
                    mma16816(acc1[s][2*j+1], aL[s], bH.z, bH.w);                 \
                }                                                                \
            }                                                                    \
        }                                                                        \
    }

    #define FILL_B1(ch, Bp)                                                          \
    {                                                                                \
        const uint4* b0 = g_w1img + ((size_t)((layer*2 + 0)*4 + (ch))*2) * 1024;     \
        const uint4* b1 = g_w1img + ((size_t)((layer*2 + 1)*4 + (ch))*2) * 1024;     \
        _Pragma("unroll")                                                            \
        for (int i = 0; i < 2; i++) cpasync16(&(Bp)[tid + i*1024],        &b0[tid + i*1024]); \
        _Pragma("unroll")                                                            \
        for (int i = 0; i < 2; i++) cpasync16(&(Bp)[2048 + tid + i*1024], &b1[tid + i*1024]); \
    }
    #define FILL_A(ch, Ap)                                                           \
    {                                                                                \
        const uint4* gA = g_aimg + ((size_t)(cta*4 + (ch))*2) * 1024;                \
        _Pragma("unroll")                                                            \
        for (int i = 0; i < 2; i++) cpasync16(&(Ap)[tid + i*1024], &gA[tid + i*1024]); \
    }

    CP_WAIT1; __syncthreads();          // B(0) ready
    G1_COMPUTE(sA0, Bb0);               // ch 0
    __syncthreads();
    FILL_A(2, sA0); FILL_B1(2, Bb0); CP_COMMIT;   // g3
    CP_WAIT1; __syncthreads();          // B(1) ready
    G1_COMPUTE(sA1, Bb1);               // ch 1
    __syncthreads();
    FILL_A(3, sA1); FILL_B1(3, Bb1); CP_COMMIT;   // g4
    CP_WAIT1; __syncthreads();          // A(2)/B(2) ready
    G1_COMPUTE(sA0, Bb0);               // ch 2
    __syncthreads();
    {   // prefetch GEMM2 B(0) into sA0 (free after ch2)
        const uint4* gB = g_w2img + ((size_t)(layer*4 + 0)*2) * 1024;
        #pragma unroll
        for (int i = 0; i < 2; i++) cpasync16(&sA0[tid + i*1024], &gB[tid + i*1024]);
        CP_COMMIT;   // g5
    }
    CP_WAIT1; __syncthreads();          // A(3)/B(3) ready
    G1_COMPUTE(sA1, Bb1);               // ch 3
    __syncthreads();                    // Bb region free -> h storage

    // ---- epilogue 1: silu + split -> h fragments (GEMM2 A layout) ----
    #pragma unroll
    for (int s = 0; s < 2; s++)
        #pragma unroll
        for (int nt = 0; nt < 4; nt++) {
            float c0 = acc1[s][nt][0], c1 = acc1[s][nt][1];
            float c2 = acc1[s][nt][2], c3 = acc1[s][nt][3];
            c0 = c0 / (1.f + __expf(-c0));
            c1 = c1 / (1.f + __expf(-c1));
            c2 = c2 / (1.f + __expf(-c2));
            c3 = c3 / (1.f + __expf(-c3));
            int C = nh*128 + (np2 + (nt >> 1))*16 + (nt & 1)*8 + tg*2;
            u32 hi01, lo01, hi23, lo23;
            split2(c0, c1, hi01, lo01);
            split2(c2, c3, hi23, lo23);
            int mtp  = mw*2 + s;
            int ktp  = C >> 4;
            int khal = (C >> 3) & 1;
            int lanep = g*4 + tg;
            u32 base = (((u32)(mtp*16 + ktp)*32 + lanep) << 2);
            hsw[base + 2*khal]             = hi01;   // row R
            hsw[base + 2*khal + 1]         = hi23;   // row R+8
            hsw[16384 + base + 2*khal]     = lo01;
            hsw[16384 + base + 2*khal + 1] = lo23;
        }
    CP_WAIT0;
    __syncthreads();

    // ===================== GEMM2 (m kept in regs -> smem) =====================
    float acc2[2][2][4];
    #pragma unroll
    for (int s = 0; s < 2; s++)
        #pragma unroll
        for (int j = 0; j < 2; j++)
            #pragma unroll
            for (int q = 0; q < 4; q++) acc2[s][j][q] = 0.f;

    uint4* B2[2] = { sA0, sA1 };
    for (int ch = 0; ch < 4; ch++) {
        if (ch < 3) {
            const uint4* gB = g_w2img + ((size_t)(layer*4 + ch + 1)*2) * 1024;
            uint4* Bnx = B2[(ch+1) & 1];
            #pragma unroll
            for (int i = 0; i < 2; i++) cpasync16(&Bnx[tid + i*1024], &gB[tid + i*1024]);
            CP_COMMIT;
        }
        const uint4* Bcur = B2[ch & 1];
        #pragma unroll
        for (int kt = 0; kt < 4; kt++) {
            int ktg = ch*4 + kt;
            uint4 aH[2], aL[2];
            #pragma unroll
            for (int s = 0; s < 2; s++) {
                int aidx = ((mw*2 + s)*16 + ktg)*32 + lane;
                aH[s] = hs4[aidx];
                aL[s] = hs4[4096 + aidx];
            }
            int idx = (nw*4 + kt)*32 + lane;
            uint4 bH = Bcur[idx];
            uint4 bL = Bcur[1024 + idx];
            #pragma unroll
            for (int s = 0; s < 2; s++) {
                mma16816(acc2[s][0], aH[s], bH.x, bH.y);
                mma16816(acc2[s][1], aH[s], bH.z, bH.w);
                mma16816(acc2[s][0], aH[s], bL.x, bL.y);
                mma16816(acc2[s][1], aH[s], bL.z, bL.w);
                mma16816(acc2[s][0], aL[s], bH.x, bH.y);
                mma16816(acc2[s][1], aL[s], bH.z, bH.w);
            }
        }
        if (ch < 3) { CP_WAIT0; __syncthreads(); }
    }
    __syncthreads();                     // all GEMM2 smem reads done (h, B dead)

    // ---- Y tile -> smem[0..38912) while m epilogue writes smem[65536..131072) ----
    {
        const uint4* gY = (const uint4*)(g_Y + (size_t)e0*KH);
        for (int i = tid; i < 2432; i += 1024) cpasync16(&((uint4*)smem)[i], &gY[i]);
        CP_COMMIT;
    }
    float* mSf = (float*)(smem + 65536);
    #pragma unroll
    for (int s = 0; s < 2; s++)
        #pragma unroll
        for (int j = 0; j < 2; j++) {
            int R = mw*32 + s*16 + g;
            int C = nw*16 + j*8 + tg*2;
            mSf[R*128 + C]       = acc2[s][j][0];
            mSf[R*128 + C + 1]   = acc2[s][j][1];
            mSf[(R+8)*128 + C]   = acc2[s][j][2];
            mSf[(R+8)*128 + C+1] = acc2[s][j][3];
        }
    CP_WAIT0;
    __syncthreads();

    // ---- fused aggregation: x[n,k,c] += 0.05 * sum_e Y[e,k]*m[e,c] ----
    {
        const float* Ysf = (const float*)smem;
        int al = tid >> 7, c = tid & 127;
        int aStart = e0 / 20;
        int n = aStart + al;
        int lo = n*20 - e0;        if (lo < 0) lo = 0;
        int hi = n*20 + 19 - e0;   if (hi > 127) hi = 127;
        if (lo <= hi) {
            float acc[KH];
            #pragma unroll
            for (int k = 0; k < KH; k++) acc[k] = 0.f;
            for (int e = lo; e <= hi; e++) {
                float mv = mSf[e*128 + c];
                #pragma unroll
                for (int k = 0; k < KH; k++) acc[k] = fmaf(Ysf[e*KH + k], mv, acc[k]);
            }
            #pragma unroll
            for (int k = 0; k < KH; k++)
                atomicAdd(&g_x[((size_t)n*KH + k)*CCH + c], 0.05f*acc[k]);
        }
    }
}

// ---------------- k_hw ----------------
__global__ void k_hw(const float* __restrict__ wf) {
    int n = blockIdx.x, lane = threadIdx.x;
    float v = 0.f;
    for (int c = lane; c < CCH; c += 32) v += g_x[(size_t)n*(KH*CCH) + c]*wf[c];
    #pragma unroll
    for (int off = 16; off; off >>= 1) v += __shfl_xor_sync(0xffffffffu, v, off);
    if (lane == 0) g_hw[n] = v;
}

// ---------------- k_out ----------------
__global__ void k_out(const float* __restrict__ Wa, const float* __restrict__ ba,
                      const int* __restrict__ ei, float* __restrict__ out) {
    int n = blockIdx.x, tid = threadIdx.x;
    __shared__ float hs[CCH];
    hs[tid] = g_x[(size_t)n*(KH*CCH) + tid];
    __syncthreads();
    if (tid < 100) {
        float acc = ba[tid];
        for (int c = 0; c < CCH; c++) acc = fmaf(hs[c], Wa[c*100 + tid], acc);
        out[NATOM*3 + n*100 + tid] = acc;
    } else if (tid < 103) {
        int j = tid - 100;
        float hwn = g_hw[n];
        float acc = 0.f;
        for (int e = 0; e < NBR; e++) {
            int ge = n*NBR + e;
            acc = fmaf(g_hw[ei[ge]] - hwn, g_dirn[ge*3 + j], acc);
        }
        out[n*3 + j] = acc;
    }
}

// ---------------- launch ----------------
static const int SMEM_S = (XS_F + YS_F)*4 + 640*4;

extern "C" void kernel_launch(void* const* d_in, const int* in_sizes, int n_in,
                              void* d_out, int out_size) {
    const float* z       = (const float*)d_in[0];
    const float* frac    = (const float*)d_in[1];
    const int*   types   = (const int*)  d_in[2];
    const float* lengths = (const float*)d_in[4];
    const float* angles  = (const float*)d_in[5];
    const int*   ei      = (const int*)  d_in[7];
    const float* emb     = (const float*)d_in[8];
    const float* zproj   = (const float*)d_in[9];
    const float* Wd      = (const float*)d_in[10];
    const float* W1      = (const float*)d_in[11];
    const float* W2      = (const float*)d_in[12];
    const float* Wa      = (const float*)d_in[13];
    const float* ba      = (const float*)d_in[14];
    const float* wf      = (const float*)d_in[15];
    float* out = (float*)d_out;

    cudaFuncSetAttribute(k_s,   cudaFuncAttributeMaxDynamicSharedMemorySize, SMEM_S);
    cudaFuncSetAttribute(k_mlp, cudaFuncAttributeMaxDynamicSharedMemorySize, SM_MLP);

    k_init <<<NCRYST, 512>>>(z, frac, lengths, angles, zproj, types, emb, ei);
    k_wconv<<<384, 256>>>(W1, Wd, W2);
    for (int l = 0; l < NLAYER; l++) {
        k_s  <<<dim3(8, NCRYST), 256, SMEM_S>>>(ei);
        k_mlp<<<NCTA_MLP, 1024, SM_MLP>>>(l);
    }
    k_hw <<<NATOM, 32>>>(wf);
    k_out<<<NATOM, 128>>>(Wa, ba, ei, out);
}

// round 14
// speedup vs baseline: 1.2502x; 1.1793x over previous
#include <cuda_runtime.h>
#include <cuda_fp16.h>
#include <math.h>
#include <stdint.h>

#define NCRYST 64
#define ATOMS  32
#define NATOM  2048
#define NBR    20
#define NEDGE  40960
#define CCH    128
#define HID    256
#define NBIN   128
#define NLAYER 8
#define KH     19
#define NCTA_MLP (NEDGE/128)     // 320

typedef unsigned long long u64;
typedef unsigned int u32;

// ---------------- scratch ----------------
__device__ float g_dirn[NEDGE * 3];
__device__ float g_Y   [NEDGE * KH];
__device__ float g_rbf [NEDGE * NBIN];
__device__ float g_x   [NATOM * KH * CCH];
__device__ float g_s   [NEDGE * CCH];
__device__ float g_hw  [NATOM];
__device__ uint4 g_w1img[8*2*4*2*1024];          // 2 MB (fp16 hi+lo)
__device__ uint4 g_w2img[8*4*2*1024];            // 1 MB (fp16 hi+lo)
__device__ uint4 g_aimg [NCTA_MLP*4*1024];       // rbf chunks 2,3 (fp16 single)

// ---------------- helpers ----------------
__device__ __forceinline__ u32 s2u(const void* p){ return (u32)__cvta_generic_to_shared(p); }
__device__ __forceinline__ void cpasync16(void* dst, const void* src){
    asm volatile("cp.async.cg.shared.global [%0], [%1], 16;" :: "r"(s2u(dst)), "l"(src));
}
#define CP_COMMIT asm volatile("cp.async.commit_group;" ::: "memory")
#define CP_WAIT0  asm volatile("cp.async.wait_group 0;" ::: "memory")
#define CP_WAIT1  asm volatile("cp.async.wait_group 1;" ::: "memory")

__device__ __forceinline__ u32 cvt2h(float v0, float v1){
    __half2 h = __floats2half2_rn(v0, v1);
    return *(u32*)&h;
}
__device__ __forceinline__ void split2h(float v0, float v1, u32& hi, u32& lo){
    __half h0 = __float2half_rn(v0);
    __half h1 = __float2half_rn(v1);
    float l0 = v0 - __half2float(h0);
    float l1 = v1 - __half2float(h1);
    __half2 H; H.x = h0; H.y = h1;
    __half2 L = __floats2half2_rn(l0, l1);
    hi = *(u32*)&H; lo = *(u32*)&L;
}
__device__ __forceinline__ void mma16816h(float* c, const uint4 a, const u32 b0, const u32 b1){
    asm volatile("mma.sync.aligned.m16n8k16.row.col.f32.f16.f16.f32 "
        "{%0,%1,%2,%3}, {%4,%5,%6,%7}, {%8,%9}, {%0,%1,%2,%3};"
        : "+f"(c[0]), "+f"(c[1]), "+f"(c[2]), "+f"(c[3])
        : "r"(a.x), "r"(a.y), "r"(a.z), "r"(a.w), "r"(b0), "r"(b1));
}

// ---------------- k_init ----------------
__global__ __launch_bounds__(512) void k_init(
        const float* __restrict__ z, const float* __restrict__ frac,
        const float* __restrict__ lengths, const float* __restrict__ angles,
        const float* __restrict__ zproj, const int* __restrict__ types,
        const float* __restrict__ emb, const int* __restrict__ ei) {
    int cb = blockIdx.x, tid = threadIdx.x;
    __shared__ float lats[9];
    __shared__ float zs[256];
    __shared__ float poss[ATOMS*3];
    __shared__ float zcs[CCH];
    __shared__ float ds[640];
    int abase = cb*ATOMS;
    int ebase = cb*640;

    if (tid == 0) {
        float a = lengths[cb*3+0], b = lengths[cb*3+1], c = lengths[cb*3+2];
        const float D2R = 0.017453292519943295f;
        float r0 = angles[cb*3+0]*D2R, r1 = angles[cb*3+1]*D2R, r2 = angles[cb*3+2]*D2R;
        float ca = cosf(r0), cbta = cosf(r1), cg = cosf(r2), sg = sinf(r2);
        float v3y = (ca - cbta*cg)/sg;
        float t = 1.0f - cbta*cbta - v3y*v3y;
        if (t < 1e-8f) t = 1e-8f;
        float v3z = sqrtf(t);
        lats[0]=a;        lats[1]=0.f;     lats[2]=0.f;
        lats[3]=b*cg;     lats[4]=b*sg;    lats[5]=0.f;
        lats[6]=c*cbta;   lats[7]=c*v3y;   lats[8]=c*v3z;
    }
    if (tid < 256) zs[tid] = z[cb*256 + tid];
    __syncthreads();
    if (tid < 96) {
        int a = tid/3, j = tid%3;
        int n = abase + a;
        poss[a*3+j] = frac[n*3+0]*lats[0+j] + frac[n*3+1]*lats[3+j] + frac[n*3+2]*lats[6+j];
    }
    if (tid < 128) {
        float acc = 0.f;
        for (int i = 0; i < 256; i++) acc += zs[i]*zproj[i*CCH + tid];
        zcs[tid] = acc;
    }
    __syncthreads();

    for (int i = tid; i < ATOMS*CCH; i += 512) {
        int a = i >> 7, c = i & 127;
        int n = abase + a;
        g_x[(size_t)(n*KH)*CCH + c] = emb[types[n]*CCH + c] + zcs[c];
    }
    for (int i4 = tid; i4 < ATOMS*18*CCH/4; i4 += 512) {
        int flat = i4*4;
        int a = flat/(18*CCH);
        int r = flat - a*(18*CCH);
        int k = 1 + (r >> 7), c = r & 127;
        *(float4*)&g_x[((size_t)(abase+a)*KH + k)*CCH + c] = make_float4(0.f,0.f,0.f,0.f);
    }

    for (int e = tid; e < 640; e += 512) {
        int s = ei[ebase + e] - abase, d = ei[NEDGE + ebase + e] - abase;
        float vx = poss[s*3+0]-poss[d*3+0];
        float vy = poss[s*3+1]-poss[d*3+1];
        float vz = poss[s*3+2]-poss[d*3+2];
        float dist = sqrtf(vx*vx + vy*vy + vz*vz) + 1e-8f;
        ds[e] = dist;
        float dx = vx/dist, dy = vy/dist, dz = vz/dist;
        int ge = ebase + e;
        g_dirn[ge*3+0]=dx; g_dirn[ge*3+1]=dy; g_dirn[ge*3+2]=dz;
        float ct = dz;
        float rho = sqrtf(dx*dx + dy*dy) + 1e-12f;
        float cph = dx/rho, sph = dy/rho;
        float P0[7]; P0[0]=1.f; P0[1]=ct;
        #pragma unroll
        for (int l=2;l<=6;l++) P0[l] = ((2*l-1)*ct*P0[l-1] - (l-1)*P0[l-2]) / l;
        float P1[7]; P1[0]=0.f; P1[1]=-rho; P1[2]=-3.f*ct*rho;
        #pragma unroll
        for (int l=3;l<=6;l++) P1[l] = ((2*l-1)*ct*P1[l-1] - l*P1[l-2]) / (l-1);
        float* Yp = &g_Y[(size_t)ge*KH];
        const float FPI = 12.566370614359172f;
        Yp[0] = 0.28209479177387814f;
        int idx = 1;
        #pragma unroll
        for (int l=1;l<=6;l++) {
            float K0 = sqrtf((2*l+1)/FPI);
            float K1 = sqrtf(2.f*(2*l+1)/(FPI*l*(l+1)));
            Yp[idx++] = K1*P1[l]*sph;
            Yp[idx++] = K0*P0[l];
            Yp[idx++] = K1*P1[l]*cph;
        }
    }
    __syncthreads();

    const float step = 8.0f/127.0f;
    const float inv  = 127.0f/8.0f;
    for (int i = tid; i < 640*NBIN; i += 512) {
        int e = i >> 7, bin = i & 127;
        float t = (ds[e] - step*(float)bin)*inv;
        g_rbf[(size_t)(ebase+e)*NBIN + bin] = expf(-0.5f*t*t);
    }
    __syncthreads();

    // bake rbf fragment images (fp16 single) for this crystal's 5 mlp-CTAs, chunks 2,3
    for (int i = tid; i < 5*2*1024; i += 512) {
        int lc  = i >> 11;
        int r   = i & 2047;
        int chl = r >> 10;
        int w   = r & 1023;
        int cta = cb*5 + lc;
        int mt = w >> 7, ktl = (w >> 5) & 3, lane = w & 31;
        int m0 = mt*16 + (lane >> 2);
        int kk = chl*64 + ktl*16 + (lane & 3)*2;
        size_t row0 = (size_t)(cta*128 + m0) * NBIN;
        size_t row1 = row0 + 8*NBIN;
        float2 p00 = *(const float2*)&g_rbf[row0 + kk];
        float2 p10 = *(const float2*)&g_rbf[row1 + kk];
        float2 p01 = *(const float2*)&g_rbf[row0 + kk + 8];
        float2 p11 = *(const float2*)&g_rbf[row1 + kk + 8];
        uint4 F;
        F.x = cvt2h(p00.x, p00.y);
        F.y = cvt2h(p10.x, p10.y);
        F.z = cvt2h(p01.x, p01.y);
        F.w = cvt2h(p11.x, p11.y);
        g_aimg[(size_t)(cta*4 + chl + 2)*1024 + w] = F;
    }
}

// ---------------- k_wconv (fp16 hi/lo) ----------------
__global__ void k_wconv(const float* __restrict__ W1, const float* __restrict__ Wd,
                        const float* __restrict__ W2) {
    int t = blockIdx.x * 256 + threadIdx.x;
    if (t < 65536) {
        int l  = t >> 13;
        int r  = t & 8191;
        int nh = r >> 12;
        int ch = (r >> 10) & 3;
        int w  = r & 1023;
        int np = w >> 7, ktl = (w >> 5) & 3, lane = w & 31;
        int nE = nh*128 + np*16 + (lane >> 2);
        int nO = nE + 8;
        int k0 = ch*64 + ktl*16 + (lane & 3)*2;
        float v[8];
        #pragma unroll
        for (int q = 0; q < 4; q++) {
            int n = (q < 2) ? nE : nO;
            int kk = k0 + ((q & 1) ? 8 : 0);
            float a0, a1;
            if (kk < 128) { a0 = W1[l*32768 + kk*256 + n];       a1 = W1[l*32768 + (kk+1)*256 + n]; }
            else          { a0 = Wd[l*32768 + (kk-128)*256 + n]; a1 = Wd[l*32768 + (kk-127)*256 + n]; }
            v[q*2] = a0; v[q*2+1] = a1;
        }
        uint4 hi, lo;
        split2h(v[0], v[1], hi.x, lo.x);
        split2h(v[2], v[3], hi.y, lo.y);
        split2h(v[4], v[5], hi.z, lo.z);
        split2h(v[6], v[7], hi.w, lo.w);
        size_t base = ((size_t)((l*2 + nh)*4 + ch)*2) * 1024 + w;
        g_w1img[base]        = hi;
        g_w1img[base + 1024] = lo;
    } else if (t < 98304) {
        int u  = t - 65536;
        int l  = u >> 12;
        int ch = (u >> 10) & 3;
        int w  = u & 1023;
        int np = w >> 7, ktl = (w >> 5) & 3, lane = w & 31;
        int nE = np*16 + (lane >> 2);
        int nO = nE + 8;
        int k0 = ch*64 + ktl*16 + (lane & 3)*2;
        float v[8];
        #pragma unroll
        for (int q = 0; q < 4; q++) {
            int n = (q < 2) ? nE : nO;
            int kk = k0 + ((q & 1) ? 8 : 0);
            v[q*2]   = W2[l*32768 + kk*128 + n];
            v[q*2+1] = W2[l*32768 + (kk+1)*128 + n];
        }
        uint4 hi, lo;
        split2h(v[0], v[1], hi.x, lo.x);
        split2h(v[2], v[3], hi.y, lo.y);
        split2h(v[4], v[5], hi.z, lo.z);
        split2h(v[6], v[7], hi.w, lo.w);
        size_t base = ((size_t)(l*4 + ch)*2) * 1024 + w;
        g_w2img[base]        = hi;
        g_w2img[base + 1024] = lo;
    }
}

// ---------------- k_s ----------------
#define XS_STRIDE 20
#define XS_F (ATOMS*KH*XS_STRIDE)
#define YS_F (640*KH)
__global__ __launch_bounds__(256, 2) void k_s(const int* __restrict__ ei) {
    int cq = blockIdx.x;
    int cb = blockIdx.y;
    int tid = threadIdx.x;
    extern __shared__ float sm[];
    float* xs  = sm;
    float* Ys  = sm + XS_F;
    int*  srcs = (int*)(Ys + YS_F);
    int abase = cb*ATOMS;
    int c0 = cq*16;
    for (int i = tid; i < ATOMS*KH*16; i += 256) {
        int a = i/(KH*16); int r = i - a*(KH*16); int k = r >> 4; int c = r & 15;
        xs[(a*KH + k)*XS_STRIDE + c] = g_x[((size_t)(abase+a)*KH + k)*CCH + c0 + c];
    }
    int ebase = cb*640;
    for (int i = tid; i < YS_F; i += 256) Ys[i] = g_Y[(size_t)ebase*KH + i];
    for (int i = tid; i < 640; i += 256) srcs[i] = ei[ebase + i] - abase;
    __syncthreads();
    int cg = tid & 3, er = tid >> 2;
    #pragma unroll 2
    for (int j = 0; j < 10; j++) {
        int e = j*64 + er;
        int sl = srcs[e];
        const float* xr = &xs[sl*(KH*XS_STRIDE) + cg*4];
        const float* yr = &Ys[e*KH];
        float4 acc = make_float4(0.f, 0.f, 0.f, 0.f);
        #pragma unroll
        for (int k = 0; k < KH; k++) {
            float y = yr[k];
            float4 xv = *(const float4*)&xr[k*XS_STRIDE];
            acc.x = fmaf(y, xv.x, acc.x);
            acc.y = fmaf(y, xv.y, acc.y);
            acc.z = fmaf(y, xv.z, acc.z);
            acc.w = fmaf(y, xv.w, acc.w);
        }
        *(float4*)&g_s[(size_t)(ebase+e)*CCH + c0 + cg*4] = acc;
    }
}

// ---------------- k_mlp: fp16 2-pass, 1024 thr, Wm4 x Wn8, fused agg ----------------
// smem: [0,16K) sA0 | [16K,32K) sA1 | (after GEMM1: [0,64K) h img)
//       [64K,128K) Bb0 (later B2 ping/pong 2x32K) | [128K,192K) Bb1 (later mS)
//       [192K, +9728) Y tile
#define SM_MLP   206336

__global__ __launch_bounds__(1024, 1) void k_mlp(int layer) {
    extern __shared__ char smem[];
    int tid = threadIdx.x;
    int wid = tid >> 5, lane = tid & 31;
    int mw = wid & 3, nw = wid >> 2;       // 4 m-warps x 8 n-warps
    int cta = blockIdx.x;
    int e0 = cta * 128;
    int g  = lane >> 2;
    int tg = lane & 3;

    uint4* sA0 = (uint4*)smem;             // 16 KB
    uint4* sA1 = (uint4*)(smem + 16384);   // 16 KB
    uint4* Bb0 = (uint4*)(smem + 65536);   // 64 KB
    uint4* Bb1 = (uint4*)(smem + 131072);  // 64 KB
    uint4* hs4 = (uint4*)smem;             // 64 KB h img after GEMM1
    u32*   hsw = (u32*)smem;

    int nh  = nw >> 2;          // 0..1 (n-half of 256)
    int np2 = (nw & 3) * 2;     // n16-pair base

    // ---- hoist s LDGs ----
    float2 sv[2][4];
    {
        int w = tid;
        int mt = w >> 7, ktl = (w >> 5) & 3, ln = w & 31;
        int m0 = mt*16 + (ln >> 2);
        int kkb = ktl*16 + (ln & 3)*2;
        size_t row0 = (size_t)(e0 + m0)*CCH;
        size_t row1 = row0 + 8*CCH;
        #pragma unroll
        for (int ch = 0; ch < 2; ch++) {
            int kk = ch*64 + kkb;
            sv[ch][0] = *(const float2*)&g_s[row0 + kk];
            sv[ch][1] = *(const float2*)&g_s[row1 + kk];
            sv[ch][2] = *(const float2*)&g_s[row0 + kk + 8];
            sv[ch][3] = *(const float2*)&g_s[row1 + kk + 8];
        }
    }

    #define FILL_B1(ch, Bp)                                                          \
    {                                                                                \
        const uint4* b0 = g_w1img + ((size_t)((layer*2 + 0)*4 + (ch))*2) * 1024;     \
        const uint4* b1 = g_w1img + ((size_t)((layer*2 + 1)*4 + (ch))*2) * 1024;     \
        _Pragma("unroll")                                                            \
        for (int i = 0; i < 2; i++) cpasync16(&(Bp)[tid + i*1024],        &b0[tid + i*1024]); \
        _Pragma("unroll")                                                            \
        for (int i = 0; i < 2; i++) cpasync16(&(Bp)[2048 + tid + i*1024], &b1[tid + i*1024]); \
    }
    #define FILL_A(ch, Ap)                                                           \
    {                                                                                \
        const uint4* gA = g_aimg + (size_t)(cta*4 + (ch))*1024;                      \
        cpasync16(&(Ap)[tid], &gA[tid]);                                             \
    }

    // ---- fill B(0); convert s; fill B(1) ----
    FILL_B1(0, Bb0); CP_COMMIT;   // g1
    #pragma unroll
    for (int ch = 0; ch < 2; ch++) {
        uint4 F;
        F.x = cvt2h(sv[ch][0].x, sv[ch][0].y);
        F.y = cvt2h(sv[ch][1].x, sv[ch][1].y);
        F.z = cvt2h(sv[ch][2].x, sv[ch][2].y);
        F.w = cvt2h(sv[ch][3].x, sv[ch][3].y);
        (ch ? sA1 : sA0)[tid] = F;
    }
    FILL_B1(1, Bb1); CP_COMMIT;   // g2

    float acc1[2][4][4];
    #pragma unroll
    for (int s = 0; s < 2; s++)
        #pragma unroll
        for (int j = 0; j < 4; j++)
            #pragma unroll
            for (int q = 0; q < 4; q++) acc1[s][j][q] = 0.f;

    #define G1_COMPUTE(Acur, Bcur)                                               \
    {                                                                            \
        _Pragma("unroll")                                                        \
        for (int kt = 0; kt < 4; kt++) {                                         \
            uint4 aF[2];                                                         \
            _Pragma("unroll")                                                    \
            for (int s = 0; s < 2; s++)                                          \
                aF[s] = (Acur)[((mw*2 + s)*4 + kt)*32 + lane];                   \
            _Pragma("unroll")                                                    \
            for (int j = 0; j < 2; j++) {                                        \
                int idx = nh*2048 + ((np2 + j)*4 + kt)*32 + lane;                \
                uint4 bH = (Bcur)[idx];                                          \
                uint4 bL = (Bcur)[1024 + idx];                                   \
                _Pragma("unroll")                                                \
                for (int s = 0; s < 2; s++) {                                    \
                    mma16816h(acc1[s][2*j],   aF[s], bH.x, bH.y);                \
                    mma16816h(acc1[s][2*j+1], aF[s], bH.z, bH.w);                \
                    mma16816h(acc1[s][2*j],   aF[s], bL.x, bL.y);                \
                    mma16816h(acc1[s][2*j+1], aF[s], bL.z, bL.w);                \
                }                                                                \
            }                                                                    \
        }                                                                        \
    }

    CP_WAIT1; __syncthreads();          // B(0) ready
    G1_COMPUTE(sA0, Bb0);               // ch 0
    __syncthreads();
    FILL_A(2, sA0); FILL_B1(2, Bb0); CP_COMMIT;   // g3
    CP_WAIT1; __syncthreads();          // B(1) ready
    G1_COMPUTE(sA1, Bb1);               // ch 1
    __syncthreads();
    FILL_A(3, sA1); FILL_B1(3, Bb1); CP_COMMIT;   // g4
    CP_WAIT1; __syncthreads();          // A(2)/B(2) ready
    G1_COMPUTE(sA0, Bb0);               // ch 2
    __syncthreads();
    {   // prefetch GEMM2 B(0) into Bb0 front (free after ch2)
        const uint4* gB = g_w2img + (size_t)(layer*4 + 0)*2048;
        #pragma unroll
        for (int i = 0; i < 2; i++) cpasync16(&Bb0[tid + i*1024], &gB[tid + i*1024]);
        CP_COMMIT;   // g5
    }
    CP_WAIT1; __syncthreads();          // A(3)/B(3) ready
    G1_COMPUTE(sA1, Bb1);               // ch 3
    __syncthreads();                    // sA region free -> h storage

    // ---- epilogue 1: silu -> fp16 h fragments (GEMM2 A layout, single img) ----
    #pragma unroll
    for (int s = 0; s < 2; s++)
        #pragma unroll
        for (int nt = 0; nt < 4; nt++) {
            float c0 = acc1[s][nt][0], c1 = acc1[s][nt][1];
            float c2 = acc1[s][nt][2], c3 = acc1[s][nt][3];
            c0 = c0 / (1.f + __expf(-c0));
            c1 = c1 / (1.f + __expf(-c1));
            c2 = c2 / (1.f + __expf(-c2));
            c3 = c3 / (1.f + __expf(-c3));
            int C = nh*128 + (np2 + (nt >> 1))*16 + (nt & 1)*8 + tg*2;
            u32 w01 = cvt2h(c0, c1);
            u32 w23 = cvt2h(c2, c3);
            int mtp  = mw*2 + s;
            int ktp  = C >> 4;
            int khal = (C >> 3) & 1;
            int lanep = g*4 + tg;
            u32 base = (((u32)(mtp*16 + ktp)*32 + lanep) << 2);
            hsw[base + 2*khal]     = w01;   // row R
            hsw[base + 2*khal + 1] = w23;   // row R+8
        }
    CP_WAIT0;
    __syncthreads();

    // ===================== GEMM2 =====================
    float acc2[2][2][4];
    #pragma unroll
    for (int s = 0; s < 2; s++)
        #pragma unroll
        for (int j = 0; j < 2; j++)
            #pragma unroll
            for (int q = 0; q < 4; q++) acc2[s][j][q] = 0.f;

    for (int ch = 0; ch < 4; ch++) {
        if (ch < 3) {
            const uint4* gB = g_w2img + (size_t)(layer*4 + ch + 1)*2048;
            uint4* Bnx = (uint4*)(smem + 65536 + (((ch+1) & 1) ? 32768 : 0));
            #pragma unroll
            for (int i = 0; i < 2; i++) cpasync16(&Bnx[tid + i*1024], &gB[tid + i*1024]);
            CP_COMMIT;
        }
        const uint4* Bcur = (const uint4*)(smem + 65536 + ((ch & 1) ? 32768 : 0));
        #pragma unroll
        for (int kt = 0; kt < 4; kt++) {
            int ktg = ch*4 + kt;
            uint4 aF[2];
            #pragma unroll
            for (int s = 0; s < 2; s++)
                aF[s] = hs4[((mw*2 + s)*16 + ktg)*32 + lane];
            int idx = (nw*4 + kt)*32 + lane;
            uint4 bH = Bcur[idx];
            uint4 bL = Bcur[1024 + idx];
            #pragma unroll
            for (int s = 0; s < 2; s++) {
                mma16816h(acc2[s][0], aF[s], bH.x, bH.y);
                mma16816h(acc2[s][1], aF[s], bH.z, bH.w);
                mma16816h(acc2[s][0], aF[s], bL.x, bL.y);
                mma16816h(acc2[s][1], aF[s], bL.z, bL.w);
            }
        }
        if (ch < 3) { CP_WAIT0; __syncthreads(); }
    }
    __syncthreads();                     // all GEMM2 smem reads done

    // ---- Y tile -> smem+196608 (608 uint4) while m epilogue writes mS (Bb1 region) ----
    {
        const uint4* gY = (const uint4*)(g_Y + (size_t)e0*KH);
        uint4* yd = (uint4*)(smem + 196608);
        if (tid < 608) cpasync16(&yd[tid], &gY[tid]);
        CP_COMMIT;
    }
    float* mSf = (float*)(smem + 131072);
    #pragma unroll
    for (int s = 0; s < 2; s++)
        #pragma unroll
        for (int j = 0; j < 2; j++) {
            int R = mw*32 + s*16 + g;
            int C = nw*16 + j*8 + tg*2;
            mSf[R*128 + C]       = acc2[s][j][0];
            mSf[R*128 + C + 1]   = acc2[s][j][1];
            mSf[(R+8)*128 + C]   = acc2[s][j][2];
            mSf[(R+8)*128 + C+1] = acc2[s][j][3];
        }
    CP_WAIT0;
    __syncthreads();

    // ---- fused aggregation: x[n,k,c] += 0.05 * sum_e Y[e,k]*m[e,c] ----
    {
        const float* Ysf = (const float*)(smem + 196608);
        int al = tid >> 7, c = tid & 127;
        int aStart = e0 / 20;
        int n = aStart + al;
        int lo = n*20 - e0;        if (lo < 0) lo = 0;
        int hi = n*20 + 19 - e0;   if (hi > 127) hi = 127;
        if (lo <= hi) {
            float acc[KH];
            #pragma unroll
            for (int k = 0; k < KH; k++) acc[k] = 0.f;
            for (int e = lo; e <= hi; e++) {
                float mv = mSf[e*128 + c];
                #pragma unroll
                for (int k = 0; k < KH; k++) acc[k] = fmaf(Ysf[e*KH + k], mv, acc[k]);
            }
            #pragma unroll
            for (int k = 0; k < KH; k++)
                atomicAdd(&g_x[((size_t)n*KH + k)*CCH + c], 0.05f*acc[k]);
        }
    }
}

// ---------------- k_hw ----------------
__global__ void k_hw(const float* __restrict__ wf) {
    int n = blockIdx.x, lane = threadIdx.x;
    float v = 0.f;
    for (int c = lane; c < CCH; c += 32) v += g_x[(size_t)n*(KH*CCH) + c]*wf[c];
    #pragma unroll
    for (int off = 16; off; off >>= 1) v += __shfl_xor_sync(0xffffffffu, v, off);
    if (lane == 0) g_hw[n] = v;
}

// ---------------- k_out ----------------
__global__ void k_out(const float* __restrict__ Wa, const float* __restrict__ ba,
                      const int* __restrict__ ei, float* __restrict__ out) {
    int n = blockIdx.x, tid = threadIdx.x;
    __shared__ float hs[CCH];
    hs[tid] = g_x[(size_t)n*(KH*CCH) + tid];
    __syncthreads();
    if (tid < 100) {
        float acc = ba[tid];
        for (int c = 0; c < CCH; c++) acc = fmaf(hs[c], Wa[c*100 + tid], acc);
        out[NATOM*3 + n*100 + tid] = acc;
    } else if (tid < 103) {
        int j = tid - 100;
        float hwn = g_hw[n];
        float acc = 0.f;
        for (int e = 0; e < NBR; e++) {
            int ge = n*NBR + e;
            acc = fmaf(g_hw[ei[ge]] - hwn, g_dirn[ge*3 + j], acc);
        }
        out[n*3 + j] = acc;
    }
}

// ---------------- launch ----------------
static const int SMEM_S = (XS_F + YS_F)*4 + 640*4;

extern "C" void kernel_launch(void* const* d_in, const int* in_sizes, int n_in,
                              void* d_out, int out_size) {
    const float* z       = (const float*)d_in[0];
    const float* frac    = (const float*)d_in[1];
    const int*   types   = (const int*)  d_in[2];
    const float* lengths = (const float*)d_in[4];
    const float* angles  = (const float*)d_in[5];
    const int*   ei      = (const int*)  d_in[7];
    const float* emb     = (const float*)d_in[8];
    const float* zproj   = (const float*)d_in[9];
    const float* Wd      = (const float*)d_in[10];
    const float* W1      = (const float*)d_in[11];
    const float* W2      = (const float*)d_in[12];
    const float* Wa      = (const float*)d_in[13];
    const float* ba      = (const float*)d_in[14];
    const float* wf      = (const float*)d_in[15];
    float* out = (float*)d_out;

    cudaFuncSetAttribute(k_s,   cudaFuncAttributeMaxDynamicSharedMemorySize, SMEM_S);
    cudaFuncSetAttribute(k_mlp, cudaFuncAttributeMaxDynamicSharedMemorySize, SM_MLP);

    k_init <<<NCRYST, 512>>>(z, frac, lengths, angles, zproj, types, emb, ei);
    k_wconv<<<384, 256>>>(W1, Wd, W2);
    for (int l = 0; l < NLAYER; l++) {
        k_s  <<<dim3(8, NCRYST), 256, SMEM_S>>>(ei);
        k_mlp<<<NCTA_MLP, 1024, SM_MLP>>>(l);
    }
    k_hw <<<NATOM, 32>>>(wf);
    k_out<<<NATOM, 128>>>(Wa, ba, ei, out);
}

// round 16
// speedup vs baseline: 1.4802x; 1.1839x over previous
#include <cuda_runtime.h>
#include <cuda_fp16.h>
#include <math.h>
#include <stdint.h>

#define NCRYST 64
#define ATOMS  32
#define NATOM  2048
#define NBR    20
#define NEDGE  40960
#define CCH    128
#define HID    256
#define NBIN   128
#define NLAYER 8
#define KH     19
#define NCTA_MLP (NEDGE/128)     // 320

typedef unsigned long long u64;
typedef unsigned int u32;

// ---------------- scratch ----------------
__device__ float g_dirn[NEDGE * 3];
__device__ float g_Y   [NEDGE * KH];
__device__ float g_rbf [NEDGE * NBIN];
__device__ float g_x   [NATOM * KH * CCH];
__device__ float g_s   [NEDGE * CCH];
__device__ float g_hw  [NATOM];
__device__ uint4 g_w1img[8*2*4*1024];            // 1 MB (fp16 single)
__device__ uint4 g_w2img[8*4*1024];              // 0.5 MB (fp16 single)
__device__ uint4 g_aimg [NCTA_MLP*4*1024];       // rbf chunks 2,3 (fp16 single)

// ---------------- helpers ----------------
__device__ __forceinline__ u32 s2u(const void* p){ return (u32)__cvta_generic_to_shared(p); }
__device__ __forceinline__ void cpasync16(void* dst, const void* src){
    asm volatile("cp.async.cg.shared.global [%0], [%1], 16;" :: "r"(s2u(dst)), "l"(src));
}
#define CP_COMMIT asm volatile("cp.async.commit_group;" ::: "memory")
#define CP_WAIT0  asm volatile("cp.async.wait_group 0;" ::: "memory")
#define CP_WAIT1  asm volatile("cp.async.wait_group 1;" ::: "memory")

__device__ __forceinline__ u32 cvt2h(float v0, float v1){
    __half2 h = __floats2half2_rn(v0, v1);
    return *(u32*)&h;
}
__device__ __forceinline__ void mma16816h(float* c, const uint4 a, const u32 b0, const u32 b1){
    asm volatile("mma.sync.aligned.m16n8k16.row.col.f32.f16.f16.f32 "
        "{%0,%1,%2,%3}, {%4,%5,%6,%7}, {%8,%9}, {%0,%1,%2,%3};"
        : "+f"(c[0]), "+f"(c[1]), "+f"(c[2]), "+f"(c[3])
        : "r"(a.x), "r"(a.y), "r"(a.z), "r"(a.w), "r"(b0), "r"(b1));
}

// ---------------- k_init ----------------
__global__ __launch_bounds__(512) void k_init(
        const float* __restrict__ z, const float* __restrict__ frac,
        const float* __restrict__ lengths, const float* __restrict__ angles,
        const float* __restrict__ zproj, const int* __restrict__ types,
        const float* __restrict__ emb, const int* __restrict__ ei) {
    int cb = blockIdx.x, tid = threadIdx.x;
    __shared__ float lats[9];
    __shared__ float zs[256];
    __shared__ float poss[ATOMS*3];
    __shared__ float zcs[CCH];
    __shared__ float ds[640];
    int abase = cb*ATOMS;
    int ebase = cb*640;

    if (tid == 0) {
        float a = lengths[cb*3+0], b = lengths[cb*3+1], c = lengths[cb*3+2];
        const float D2R = 0.017453292519943295f;
        float r0 = angles[cb*3+0]*D2R, r1 = angles[cb*3+1]*D2R, r2 = angles[cb*3+2]*D2R;
        float ca = cosf(r0), cbta = cosf(r1), cg = cosf(r2), sg = sinf(r2);
        float v3y = (ca - cbta*cg)/sg;
        float t = 1.0f - cbta*cbta - v3y*v3y;
        if (t < 1e-8f) t = 1e-8f;
        float v3z = sqrtf(t);
        lats[0]=a;        lats[1]=0.f;     lats[2]=0.f;
        lats[3]=b*cg;     lats[4]=b*sg;    lats[5]=0.f;
        lats[6]=c*cbta;   lats[7]=c*v3y;   lats[8]=c*v3z;
    }
    if (tid < 256) zs[tid] = z[cb*256 + tid];
    __syncthreads();
    if (tid < 96) {
        int a = tid/3, j = tid%3;
        int n = abase + a;
        poss[a*3+j] = frac[n*3+0]*lats[0+j] + frac[n*3+1]*lats[3+j] + frac[n*3+2]*lats[6+j];
    }
    if (tid < 128) {
        float acc = 0.f;
        for (int i = 0; i < 256; i++) acc += zs[i]*zproj[i*CCH + tid];
        zcs[tid] = acc;
    }
    __syncthreads();

    for (int i = tid; i < ATOMS*CCH; i += 512) {
        int a = i >> 7, c = i & 127;
        int n = abase + a;
        g_x[(size_t)(n*KH)*CCH + c] = emb[types[n]*CCH + c] + zcs[c];
    }
    for (int i4 = tid; i4 < ATOMS*18*CCH/4; i4 += 512) {
        int flat = i4*4;
        int a = flat/(18*CCH);
        int r = flat - a*(18*CCH);
        int k = 1 + (r >> 7), c = r & 127;
        *(float4*)&g_x[((size_t)(abase+a)*KH + k)*CCH + c] = make_float4(0.f,0.f,0.f,0.f);
    }

    for (int e = tid; e < 640; e += 512) {
        int s = ei[ebase + e] - abase, d = ei[NEDGE + ebase + e] - abase;
        float vx = poss[s*3+0]-poss[d*3+0];
        float vy = poss[s*3+1]-poss[d*3+1];
        float vz = poss[s*3+2]-poss[d*3+2];
        float dist = sqrtf(vx*vx + vy*vy + vz*vz) + 1e-8f;
        ds[e] = dist;
        float dx = vx/dist, dy = vy/dist, dz = vz/dist;
        int ge = ebase + e;
        g_dirn[ge*3+0]=dx; g_dirn[ge*3+1]=dy; g_dirn[ge*3+2]=dz;
        float ct = dz;
        float rho = sqrtf(dx*dx + dy*dy) + 1e-12f;
        float cph = dx/rho, sph = dy/rho;
        float P0[7]; P0[0]=1.f; P0[1]=ct;
        #pragma unroll
        for (int l=2;l<=6;l++) P0[l] = ((2*l-1)*ct*P0[l-1] - (l-1)*P0[l-2]) / l;
        float P1[7]; P1[0]=0.f; P1[1]=-rho; P1[2]=-3.f*ct*rho;
        #pragma unroll
        for (int l=3;l<=6;l++) P1[l] = ((2*l-1)*ct*P1[l-1] - l*P1[l-2]) / (l-1);
        float* Yp = &g_Y[(size_t)ge*KH];
        const float FPI = 12.566370614359172f;
        Yp[0] = 0.28209479177387814f;
        int idx = 1;
        #pragma unroll
        for (int l=1;l<=6;l++) {
            float K0 = sqrtf((2*l+1)/FPI);
            float K1 = sqrtf(2.f*(2*l+1)/(FPI*l*(l+1)));
            Yp[idx++] = K1*P1[l]*sph;
            Yp[idx++] = K0*P0[l];
            Yp[idx++] = K1*P1[l]*cph;
        }
    }
    __syncthreads();

    const float step = 8.0f/127.0f;
    const float inv  = 127.0f/8.0f;
    for (int i = tid; i < 640*NBIN; i += 512) {
        int e = i >> 7, bin = i & 127;
        float t = (ds[e] - step*(float)bin)*inv;
        g_rbf[(size_t)(ebase+e)*NBIN + bin] = expf(-0.5f*t*t);
    }
    __syncthreads();

    // bake rbf fragment images (fp16 single) chunks 2,3
    for (int i = tid; i < 5*2*1024; i += 512) {
        int lc  = i >> 11;
        int r   = i & 2047;
        int chl = r >> 10;
        int w   = r & 1023;
        int cta = cb*5 + lc;
        int mt = w >> 7, ktl = (w >> 5) & 3, lane = w & 31;
        int m0 = mt*16 + (lane >> 2);
        int kk = chl*64 + ktl*16 + (lane & 3)*2;
        size_t row0 = (size_t)(cta*128 + m0) * NBIN;
        size_t row1 = row0 + 8*NBIN;
        float2 p00 = *(const float2*)&g_rbf[row0 + kk];
        float2 p10 = *(const float2*)&g_rbf[row1 + kk];
        float2 p01 = *(const float2*)&g_rbf[row0 + kk + 8];
        float2 p11 = *(const float2*)&g_rbf[row1 + kk + 8];
        uint4 F;
        F.x = cvt2h(p00.x, p00.y);
        F.y = cvt2h(p10.x, p10.y);
        F.z = cvt2h(p01.x, p01.y);
        F.w = cvt2h(p11.x, p11.y);
        g_aimg[(size_t)(cta*4 + chl + 2)*1024 + w] = F;
    }
}

// ---------------- k_wconv (fp16 single) — CLEAN decode ----------------
// W1cat image: t in [0, 65536): l=t>>13, nh=(t>>12)&1, ch=(t>>10)&3, w=t&1023
// W2 image:    t in [65536, 98304): u=t-65536, l=u>>12, ch=(u>>10)&3, w=u&1023
__global__ void k_wconv(const float* __restrict__ W1, const float* __restrict__ Wd,
                        const float* __restrict__ W2) {
    int t = blockIdx.x * 256 + threadIdx.x;
    if (t < 65536) {
        int l  = t >> 13;
        int nh = (t >> 12) & 1;
        int ch = (t >> 10) & 3;
        int w  = t & 1023;
        int np = w >> 7, ktl = (w >> 5) & 3, lane = w & 31;
        int nE = nh*128 + np*16 + (lane >> 2);
        int nO = nE + 8;
        int k0 = ch*64 + ktl*16 + (lane & 3)*2;
        float v[8];
        #pragma unroll
        for (int q = 0; q < 4; q++) {
            int n = (q < 2) ? nE : nO;
            int kk = k0 + ((q & 1) ? 8 : 0);
            float a0, a1;
            if (kk < 128) { a0 = W1[l*32768 + kk*256 + n];       a1 = W1[l*32768 + (kk+1)*256 + n]; }
            else          { a0 = Wd[l*32768 + (kk-128)*256 + n]; a1 = Wd[l*32768 + (kk-127)*256 + n]; }
            v[q*2] = a0; v[q*2+1] = a1;
        }
        uint4 F;
        F.x = cvt2h(v[0], v[1]);
        F.y = cvt2h(v[2], v[3]);
        F.z = cvt2h(v[4], v[5]);
        F.w = cvt2h(v[6], v[7]);
        g_w1img[(size_t)((l*2 + nh)*4 + ch)*1024 + w] = F;
    } else if (t < 98304) {
        int u  = t - 65536;
        int l  = u >> 12;
        int ch = (u >> 10) & 3;
        int w  = u & 1023;
        int np = w >> 7, ktl = (w >> 5) & 3, lane = w & 31;
        int nE = np*16 + (lane >> 2);
        int nO = nE + 8;
        int k0 = ch*64 + ktl*16 + (lane & 3)*2;
        float v[8];
        #pragma unroll
        for (int q = 0; q < 4; q++) {
            int n = (q < 2) ? nE : nO;
            int kk = k0 + ((q & 1) ? 8 : 0);
            v[q*2]   = W2[l*32768 + kk*128 + n];
            v[q*2+1] = W2[l*32768 + (kk+1)*128 + n];
        }
        uint4 F;
        F.x = cvt2h(v[0], v[1]);
        F.y = cvt2h(v[2], v[3]);
        F.z = cvt2h(v[4], v[5]);
        F.w = cvt2h(v[6], v[7]);
        g_w2img[(size_t)(l*4 + ch)*1024 + w] = F;
    }
}

// ---------------- k_s ----------------
#define XS_STRIDE 20
#define XS_F (ATOMS*KH*XS_STRIDE)
#define YS_F (640*KH)
__global__ __launch_bounds__(256, 2) void k_s(const int* __restrict__ ei) {
    int cq = blockIdx.x;
    int cb = blockIdx.y;
    int tid = threadIdx.x;
    extern __shared__ float sm[];
    float* xs  = sm;
    float* Ys  = sm + XS_F;
    int*  srcs = (int*)(Ys + YS_F);
    int abase = cb*ATOMS;
    int c0 = cq*16;
    for (int i = tid; i < ATOMS*KH*16; i += 256) {
        int a = i/(KH*16); int r = i - a*(KH*16); int k = r >> 4; int c = r & 15;
        xs[(a*KH + k)*XS_STRIDE + c] = g_x[((size_t)(abase+a)*KH + k)*CCH + c0 + c];
    }
    int ebase = cb*640;
    for (int i = tid; i < YS_F; i += 256) Ys[i] = g_Y[(size_t)ebase*KH + i];
    for (int i = tid; i < 640; i += 256) srcs[i] = ei[ebase + i] - abase;
    __syncthreads();
    int cg = tid & 3, er = tid >> 2;
    #pragma unroll 2
    for (int j = 0; j < 10; j++) {
        int e = j*64 + er;
        int sl = srcs[e];
        const float* xr = &xs[sl*(KH*XS_STRIDE) + cg*4];
        const float* yr = &Ys[e*KH];
        float4 acc = make_float4(0.f, 0.f, 0.f, 0.f);
        #pragma unroll
        for (int k = 0; k < KH; k++) {
            float y = yr[k];
            float4 xv = *(const float4*)&xr[k*XS_STRIDE];
            acc.x = fmaf(y, xv.x, acc.x);
            acc.y = fmaf(y, xv.y, acc.y);
            acc.z = fmaf(y, xv.z, acc.z);
            acc.w = fmaf(y, xv.w, acc.w);
        }
        *(float4*)&g_s[(size_t)(ebase+e)*CCH + c0 + cg*4] = acc;
    }
}

// ---------------- k_mlp: fp16 single-pass A and B, 1024 thr, fused agg ----------------
#define SM_MLP   206336

__global__ __launch_bounds__(1024, 1) void k_mlp(int layer) {
    extern __shared__ char smem[];
    int tid = threadIdx.x;
    int wid = tid >> 5, lane = tid & 31;
    int mw = wid & 3, nw = wid >> 2;       // 4 m-warps x 8 n-warps
    int cta = blockIdx.x;
    int e0 = cta * 128;
    int g  = lane >> 2;
    int tg = lane & 3;

    uint4* sA0 = (uint4*)smem;             // 16 KB
    uint4* sA1 = (uint4*)(smem + 16384);   // 16 KB
    uint4* Bb0 = (uint4*)(smem + 65536);   // 32 KB
    uint4* Bb1 = (uint4*)(smem + 98304);   // 32 KB
    uint4* hs4 = (uint4*)smem;             // 64 KB h img after GEMM1
    u32*   hsw = (u32*)smem;

    int nh  = nw >> 2;          // 0..1
    int np2 = (nw & 3) * 2;     // n16-pair base

    // ---- hoist s LDGs ----
    float2 sv[2][4];
    {
        int w = tid;
        int mt = w >> 7, ktl = (w >> 5) & 3, ln = w & 31;
        int m0 = mt*16 + (ln >> 2);
        int kkb = ktl*16 + (ln & 3)*2;
        size_t row0 = (size_t)(e0 + m0)*CCH;
        size_t row1 = row0 + 8*CCH;
        #pragma unroll
        for (int ch = 0; ch < 2; ch++) {
            int kk = ch*64 + kkb;
            sv[ch][0] = *(const float2*)&g_s[row0 + kk];
            sv[ch][1] = *(const float2*)&g_s[row1 + kk];
            sv[ch][2] = *(const float2*)&g_s[row0 + kk + 8];
            sv[ch][3] = *(const float2*)&g_s[row1 + kk + 8];
        }
    }

    #define FILL_B1(ch, Bp)                                                          \
    {                                                                                \
        const uint4* b0 = g_w1img + (size_t)((layer*2 + 0)*4 + (ch))*1024;           \
        const uint4* b1 = g_w1img + (size_t)((layer*2 + 1)*4 + (ch))*1024;           \
        cpasync16(&(Bp)[tid],        &b0[tid]);                                      \
        cpasync16(&(Bp)[1024 + tid], &b1[tid]);                                      \
    }
    #define FILL_A(ch, Ap)                                                           \
    {                                                                                \
        const uint4* gA = g_aimg + (size_t)(cta*4 + (ch))*1024;                      \
        cpasync16(&(Ap)[tid], &gA[tid]);                                             \
    }

    FILL_B1(0, Bb0); CP_COMMIT;   // g1
    #pragma unroll
    for (int ch = 0; ch < 2; ch++) {
        uint4 F;
        F.x = cvt2h(sv[ch][0].x, sv[ch][0].y);
        F.y = cvt2h(sv[ch][1].x, sv[ch][1].y);
        F.z = cvt2h(sv[ch][2].x, sv[ch][2].y);
        F.w = cvt2h(sv[ch][3].x, sv[ch][3].y);
        (ch ? sA1 : sA0)[tid] = F;
    }
    FILL_B1(1, Bb1); CP_COMMIT;   // g2

    float acc1[2][4][4];
    #pragma unroll
    for (int s = 0; s < 2; s++)
        #pragma unroll
        for (int j = 0; j < 4; j++)
            #pragma unroll
            for (int q = 0; q < 4; q++) acc1[s][j][q] = 0.f;

    #define G1_COMPUTE(Acur, Bcur)                                               \
    {                                                                            \
        _Pragma("unroll")                                                        \
        for (int kt = 0; kt < 4; kt++) {                                         \
            uint4 aF[2];                                                         \
            _Pragma("unroll")                                                    \
            for (int s = 0; s < 2; s++)                                          \
                aF[s] = (Acur)[((mw*2 + s)*4 + kt)*32 + lane];                   \
            _Pragma("unroll")                                                    \
            for (int j = 0; j < 2; j++) {                                        \
                uint4 bF = (Bcur)[nh*1024 + ((np2 + j)*4 + kt)*32 + lane];       \
                _Pragma("unroll")                                                \
                for (int s = 0; s < 2; s++) {                                    \
                    mma16816h(acc1[s][2*j],   aF[s], bF.x, bF.y);                \
                    mma16816h(acc1[s][2*j+1], aF[s], bF.z, bF.w);                \
                }                                                                \
            }                                                                    \
        }                                                                        \
    }

    CP_WAIT1; __syncthreads();          // B(0) ready
    G1_COMPUTE(sA0, Bb0);               // ch 0
    __syncthreads();
    FILL_A(2, sA0); FILL_B1(2, Bb0); CP_COMMIT;   // g3
    CP_WAIT1; __syncthreads();          // B(1) ready
    G1_COMPUTE(sA1, Bb1);               // ch 1
    __syncthreads();
    FILL_A(3, sA1); FILL_B1(3, Bb1); CP_COMMIT;   // g4
    CP_WAIT1; __syncthreads();          // A(2)/B(2) ready
    G1_COMPUTE(sA0, Bb0);               // ch 2
    __syncthreads();
    {   // prefetch GEMM2 B(0) into Bb0 front
        const uint4* gB = g_w2img + (size_t)(layer*4 + 0)*1024;
        cpasync16(&Bb0[tid], &gB[tid]);
        CP_COMMIT;   // g5
    }
    CP_WAIT1; __syncthreads();          // A(3)/B(3) ready
    G1_COMPUTE(sA1, Bb1);               // ch 3
    __syncthreads();                    // sA region free -> h storage

    // ---- epilogue 1: silu -> fp16 h fragments ----
    #pragma unroll
    for (int s = 0; s < 2; s++)
        #pragma unroll
        for (int nt = 0; nt < 4; nt++) {
            float c0 = acc1[s][nt][0], c1 = acc1[s][nt][1];
            float c2 = acc1[s][nt][2], c3 = acc1[s][nt][3];
            c0 = c0 / (1.f + __expf(-c0));
            c1 = c1 / (1.f + __expf(-c1));
            c2 = c2 / (1.f + __expf(-c2));
            c3 = c3 / (1.f + __expf(-c3));
            int C = nh*128 + (np2 + (nt >> 1))*16 + (nt & 1)*8 + tg*2;
            u32 w01 = cvt2h(c0, c1);
            u32 w23 = cvt2h(c2, c3);
            int mtp  = mw*2 + s;
            int ktp  = C >> 4;
            int khal = (C >> 3) & 1;
            int lanep = g*4 + tg;
            u32 base = (((u32)(mtp*16 + ktp)*32 + lanep) << 2);
            hsw[base + 2*khal]     = w01;
            hsw[base + 2*khal + 1] = w23;
        }
    CP_WAIT0;
    __syncthreads();

    // ===================== GEMM2 (B ping/pong 16KB @65536/81920) =====================
    float acc2[2][2][4];
    #pragma unroll
    for (int s = 0; s < 2; s++)
        #pragma unroll
        for (int j = 0; j < 2; j++)
            #pragma unroll
            for (int q = 0; q < 4; q++) acc2[s][j][q] = 0.f;

    for (int ch = 0; ch < 4; ch++) {
        if (ch < 3) {
            const uint4* gB = g_w2img + (size_t)(layer*4 + ch + 1)*1024;
            uint4* Bnx = (uint4*)(smem + 65536 + (((ch+1) & 1) ? 16384 : 0));
            cpasync16(&Bnx[tid], &gB[tid]);
            CP_COMMIT;
        }
        const uint4* Bcur = (const uint4*)(smem + 65536 + ((ch & 1) ? 16384 : 0));
        #pragma unroll
        for (int kt = 0; kt < 4; kt++) {
            int ktg = ch*4 + kt;
            uint4 aF[2];
            #pragma unroll
            for (int s = 0; s < 2; s++)
                aF[s] = hs4[((mw*2 + s)*16 + ktg)*32 + lane];
            uint4 bF = Bcur[(nw*4 + kt)*32 + lane];
            #pragma unroll
            for (int s = 0; s < 2; s++) {
                mma16816h(acc2[s][0], aF[s], bF.x, bF.y);
                mma16816h(acc2[s][1], aF[s], bF.z, bF.w);
            }
        }
        if (ch < 3) { CP_WAIT0; __syncthreads(); }
    }
    __syncthreads();

    // ---- Y tile cp.async + m epilogue ----
    {
        const uint4* gY = (const uint4*)(g_Y + (size_t)e0*KH);
        uint4* yd = (uint4*)(smem + 196608);
        if (tid < 608) cpasync16(&yd[tid], &gY[tid]);
        CP_COMMIT;
    }
    float* mSf = (float*)(smem + 131072);
    #pragma unroll
    for (int s = 0; s < 2; s++)
        #pragma unroll
        for (int j = 0; j < 2; j++) {
            int R = mw*32 + s*16 + g;
            int C = nw*16 + j*8 + tg*2;
            mSf[R*128 + C]       = acc2[s][j][0];
            mSf[R*128 + C + 1]   = acc2[s][j][1];
            mSf[(R+8)*128 + C]   = acc2[s][j][2];
            mSf[(R+8)*128 + C+1] = acc2[s][j][3];
        }
    CP_WAIT0;
    __syncthreads();

    // ---- fused aggregation ----
    {
        const float* Ysf = (const float*)(smem + 196608);
        int al = tid >> 7, c = tid & 127;
        int aStart = e0 / 20;
        int n = aStart + al;
        int lo = n*20 - e0;        if (lo < 0) lo = 0;
        int hi = n*20 + 19 - e0;   if (hi > 127) hi = 127;
        if (lo <= hi) {
            float acc[KH];
            #pragma unroll
            for (int k = 0; k < KH; k++) acc[k] = 0.f;
            for (int e = lo; e <= hi; e++) {
                float mv = mSf[e*128 + c];
                #pragma unroll
                for (int k = 0; k < KH; k++) acc[k] = fmaf(Ysf[e*KH + k], mv, acc[k]);
            }
            #pragma unroll
            for (int k = 0; k < KH; k++)
                atomicAdd(&g_x[((size_t)n*KH + k)*CCH + c], 0.05f*acc[k]);
        }
    }
}

// ---------------- k_hw ----------------
__global__ void k_hw(const float* __restrict__ wf) {
    int n = blockIdx.x, lane = threadIdx.x;
    float v = 0.f;
    for (int c = lane; c < CCH; c += 32) v += g_x[(size_t)n*(KH*CCH) + c]*wf[c];
    #pragma unroll
    for (int off = 16; off; off >>= 1) v += __shfl_xor_sync(0xffffffffu, v, off);
    if (lane == 0) g_hw[n] = v;
}

// ---------------- k_out ----------------
__global__ void k_out(const float* __restrict__ Wa, const float* __restrict__ ba,
                      const int* __restrict__ ei, float* __restrict__ out) {
    int n = blockIdx.x, tid = threadIdx.x;
    __shared__ float hs[CCH];
    hs[tid] = g_x[(size_t)n*(KH*CCH) + tid];
    __syncthreads();
    if (tid < 100) {
        float acc = ba[tid];
        for (int c = 0; c < CCH; c++) acc = fmaf(hs[c], Wa[c*100 + tid], acc);
        out[NATOM*3 + n*100 + tid] = acc;
    } else if (tid < 103) {
        int j = tid - 100;
        float hwn = g_hw[n];
        float acc = 0.f;
        for (int e = 0; e < NBR; e++) {
            int ge = n*NBR + e;
            acc = fmaf(g_hw[ei[ge]] - hwn, g_dirn[ge*3 + j], acc);
        }
        out[n*3 + j] = acc;
    }
}

// ---------------- launch ----------------
static const int SMEM_S = (XS_F + YS_F)*4 + 640*4;

extern "C" void kernel_launch(void* const* d_in, const int* in_sizes, int n_in,
                              void* d_out, int out_size) {
    const float* z       = (const float*)d_in[0];
    const float* frac    = (const float*)d_in[1];
    const int*   types   = (const int*)  d_in[2];
    const float* lengths = (const float*)d_in[4];
    const float* angles  = (const float*)d_in[5];
    const int*   ei      = (const int*)  d_in[7];
    const float* emb     = (const float*)d_in[8];
    const float* zproj   = (const float*)d_in[9];
    const float* Wd      = (const float*)d_in[10];
    const float* W1      = (const float*)d_in[11];
    const float* W2      = (const float*)d_in[12];
    const float* Wa      = (const float*)d_in[13];
    const float* ba      = (const float*)d_in[14];
    const float* wf      = (const float*)d_in[15];
    float* out = (float*)d_out;

    cudaFuncSetAttribute(k_s,   cudaFuncAttributeMaxDynamicSharedMemorySize, SMEM_S);
    cudaFuncSetAttribute(k_mlp, cudaFuncAttributeMaxDynamicSharedMemorySize, SM_MLP);

    k_init <<<NCRYST, 512>>>(z, frac, lengths, angles, zproj, types, emb, ei);
    k_wconv<<<384, 256>>>(W1, Wd, W2);
    for (int l = 0; l < NLAYER; l++) {
        k_s  <<<dim3(8, NCRYST), 256, SMEM_S>>>(ei);
        k_mlp<<<NCTA_MLP, 1024, SM_MLP>>>(l);
    }
    k_hw <<<NATOM, 32>>>(wf);
    k_out<<<NATOM, 128>>>(Wa, ba, ei, out);
}

// round 17
// speedup vs baseline: 1.4964x; 1.0109x over previous
#include <cuda_runtime.h>
#include <cuda_fp16.h>
#include <math.h>
#include <stdint.h>

#define NCRYST 64
#define ATOMS  32
#define NATOM  2048
#define NBR    20
#define NEDGE  40960
#define CCH    128
#define HID    256
#define NBIN   128
#define NLAYER 8
#define KH     19
#define NCTA_MLP (NEDGE/128)     // 320

typedef unsigned long long u64;
typedef unsigned int u32;

// ---------------- scratch ----------------
__device__ float  g_dirn[NEDGE * 3];
__device__ float  g_Y   [NEDGE * KH];
__device__ float  g_rbf [NEDGE * NBIN];
__device__ float  g_x   [NATOM * KH * CCH];
__device__ __half g_s   [NEDGE * CCH];           // fp16 now
__device__ float  g_hw  [NATOM];
__device__ uint4  g_w1img[8*2*4*1024];           // 1 MB (fp16 single)
__device__ uint4  g_w2img[8*4*1024];             // 0.5 MB (fp16 single)
__device__ uint4  g_aimg [NCTA_MLP*4*1024];      // rbf chunks 2,3 (fp16 single)

// ---------------- helpers ----------------
__device__ __forceinline__ u32 s2u(const void* p){ return (u32)__cvta_generic_to_shared(p); }
__device__ __forceinline__ void cpasync16(void* dst, const void* src){
    asm volatile("cp.async.cg.shared.global [%0], [%1], 16;" :: "r"(s2u(dst)), "l"(src));
}
#define CP_COMMIT asm volatile("cp.async.commit_group;" ::: "memory")
#define CP_WAIT0  asm volatile("cp.async.wait_group 0;" ::: "memory")
#define CP_WAIT1  asm volatile("cp.async.wait_group 1;" ::: "memory")

__device__ __forceinline__ u32 cvt2h(float v0, float v1){
    __half2 h = __floats2half2_rn(v0, v1);
    return *(u32*)&h;
}
__device__ __forceinline__ void mma16816h(float* c, const uint4 a, const u32 b0, const u32 b1){
    asm volatile("mma.sync.aligned.m16n8k16.row.col.f32.f16.f16.f32 "
        "{%0,%1,%2,%3}, {%4,%5,%6,%7}, {%8,%9}, {%0,%1,%2,%3};"
        : "+f"(c[0]), "+f"(c[1]), "+f"(c[2]), "+f"(c[3])
        : "r"(a.x), "r"(a.y), "r"(a.z), "r"(a.w), "r"(b0), "r"(b1));
}

// ---------------- k_init ----------------
__global__ __launch_bounds__(512) void k_init(
        const float* __restrict__ z, const float* __restrict__ frac,
        const float* __restrict__ lengths, const float* __restrict__ angles,
        const float* __restrict__ zproj, const int* __restrict__ types,
        const float* __restrict__ emb, const int* __restrict__ ei) {
    int cb = blockIdx.x, tid = threadIdx.x;
    __shared__ float lats[9];
    __shared__ float zs[256];
    __shared__ float poss[ATOMS*3];
    __shared__ float zcs[CCH];
    __shared__ float ds[640];
    int abase = cb*ATOMS;
    int ebase = cb*640;

    if (tid == 0) {
        float a = lengths[cb*3+0], b = lengths[cb*3+1], c = lengths[cb*3+2];
        const float D2R = 0.017453292519943295f;
        float r0 = angles[cb*3+0]*D2R, r1 = angles[cb*3+1]*D2R, r2 = angles[cb*3+2]*D2R;
        float ca = cosf(r0), cbta = cosf(r1), cg = cosf(r2), sg = sinf(r2);
        float v3y = (ca - cbta*cg)/sg;
        float t = 1.0f - cbta*cbta - v3y*v3y;
        if (t < 1e-8f) t = 1e-8f;
        float v3z = sqrtf(t);
        lats[0]=a;        lats[1]=0.f;     lats[2]=0.f;
        lats[3]=b*cg;     lats[4]=b*sg;    lats[5]=0.f;
        lats[6]=c*cbta;   lats[7]=c*v3y;   lats[8]=c*v3z;
    }
    if (tid < 256) zs[tid] = z[cb*256 + tid];
    __syncthreads();
    if (tid < 96) {
        int a = tid/3, j = tid%3;
        int n = abase + a;
        poss[a*3+j] = frac[n*3+0]*lats[0+j] + frac[n*3+1]*lats[3+j] + frac[n*3+2]*lats[6+j];
    }
    if (tid < 128) {
        float acc = 0.f;
        for (int i = 0; i < 256; i++) acc += zs[i]*zproj[i*CCH + tid];
        zcs[tid] = acc;
    }
    __syncthreads();

    for (int i = tid; i < ATOMS*CCH; i += 512) {
        int a = i >> 7, c = i & 127;
        int n = abase + a;
        g_x[(size_t)(n*KH)*CCH + c] = emb[types[n]*CCH + c] + zcs[c];
    }
    for (int i4 = tid; i4 < ATOMS*18*CCH/4; i4 += 512) {
        int flat = i4*4;
        int a = flat/(18*CCH);
        int r = flat - a*(18*CCH);
        int k = 1 + (r >> 7), c = r & 127;
        *(float4*)&g_x[((size_t)(abase+a)*KH + k)*CCH + c] = make_float4(0.f,0.f,0.f,0.f);
    }

    for (int e = tid; e < 640; e += 512) {
        int s = ei[ebase + e] - abase, d = ei[NEDGE + ebase + e] - abase;
        float vx = poss[s*3+0]-poss[d*3+0];
        float vy = poss[s*3+1]-poss[d*3+1];
        float vz = poss[s*3+2]-poss[d*3+2];
        float dist = sqrtf(vx*vx + vy*vy + vz*vz) + 1e-8f;
        ds[e] = dist;
        float dx = vx/dist, dy = vy/dist, dz = vz/dist;
        int ge = ebase + e;
        g_dirn[ge*3+0]=dx; g_dirn[ge*3+1]=dy; g_dirn[ge*3+2]=dz;
        float ct = dz;
        float rho = sqrtf(dx*dx + dy*dy) + 1e-12f;
        float cph = dx/rho, sph = dy/rho;
        float P0[7]; P0[0]=1.f; P0[1]=ct;
        #pragma unroll
        for (int l=2;l<=6;l++) P0[l] = ((2*l-1)*ct*P0[l-1] - (l-1)*P0[l-2]) / l;
        float P1[7]; P1[0]=0.f; P1[1]=-rho; P1[2]=-3.f*ct*rho;
        #pragma unroll
        for (int l=3;l<=6;l++) P1[l] = ((2*l-1)*ct*P1[l-1] - l*P1[l-2]) / (l-1);
        float* Yp = &g_Y[(size_t)ge*KH];
        const float FPI = 12.566370614359172f;
        Yp[0] = 0.28209479177387814f;
        int idx = 1;
        #pragma unroll
        for (int l=1;l<=6;l++) {
            float K0 = sqrtf((2*l+1)/FPI);
            float K1 = sqrtf(2.f*(2*l+1)/(FPI*l*(l+1)));
            Yp[idx++] = K1*P1[l]*sph;
            Yp[idx++] = K0*P0[l];
            Yp[idx++] = K1*P1[l]*cph;
        }
    }
    __syncthreads();

    const float step = 8.0f/127.0f;
    const float inv  = 127.0f/8.0f;
    for (int i = tid; i < 640*NBIN; i += 512) {
        int e = i >> 7, bin = i & 127;
        float t = (ds[e] - step*(float)bin)*inv;
        g_rbf[(size_t)(ebase+e)*NBIN + bin] = expf(-0.5f*t*t);
    }
    __syncthreads();

    // bake rbf fragment images (fp16 single) chunks 2,3
    for (int i = tid; i < 5*2*1024; i += 512) {
        int lc  = i >> 11;
        int r   = i & 2047;
        int chl = r >> 10;
        int w   = r & 1023;
        int cta = cb*5 + lc;
        int mt = w >> 7, ktl = (w >> 5) & 3, lane = w & 31;
        int m0 = mt*16 + (lane >> 2);
        int kk = chl*64 + ktl*16 + (lane & 3)*2;
        size_t row0 = (size_t)(cta*128 + m0) * NBIN;
        size_t row1 = row0 + 8*NBIN;
        float2 p00 = *(const float2*)&g_rbf[row0 + kk];
        float2 p10 = *(const float2*)&g_rbf[row1 + kk];
        float2 p01 = *(const float2*)&g_rbf[row0 + kk + 8];
        float2 p11 = *(const float2*)&g_rbf[row1 + kk + 8];
        uint4 F;
        F.x = cvt2h(p00.x, p00.y);
        F.y = cvt2h(p10.x, p10.y);
        F.z = cvt2h(p01.x, p01.y);
        F.w = cvt2h(p11.x, p11.y);
        g_aimg[(size_t)(cta*4 + chl + 2)*1024 + w] = F;
    }
}

// ---------------- k_wconv (fp16 single) ----------------
__global__ void k_wconv(const float* __restrict__ W1, const float* __restrict__ Wd,
                        const float* __restrict__ W2) {
    int t = blockIdx.x * 256 + threadIdx.x;
    if (t < 65536) {
        int l  = t >> 13;
        int nh = (t >> 12) & 1;
        int ch = (t >> 10) & 3;
        int w  = t & 1023;
        int np = w >> 7, ktl = (w >> 5) & 3, lane = w & 31;
        int nE = nh*128 + np*16 + (lane >> 2);
        int nO = nE + 8;
        int k0 = ch*64 + ktl*16 + (lane & 3)*2;
        float v[8];
        #pragma unroll
        for (int q = 0; q < 4; q++) {
            int n = (q < 2) ? nE : nO;
            int kk = k0 + ((q & 1) ? 8 : 0);
            float a0, a1;
            if (kk < 128) { a0 = W1[l*32768 + kk*256 + n];       a1 = W1[l*32768 + (kk+1)*256 + n]; }
            else          { a0 = Wd[l*32768 + (kk-128)*256 + n]; a1 = Wd[l*32768 + (kk-127)*256 + n]; }
            v[q*2] = a0; v[q*2+1] = a1;
        }
        uint4 F;
        F.x = cvt2h(v[0], v[1]);
        F.y = cvt2h(v[2], v[3]);
        F.z = cvt2h(v[4], v[5]);
        F.w = cvt2h(v[6], v[7]);
        g_w1img[(size_t)((l*2 + nh)*4 + ch)*1024 + w] = F;
    } else if (t < 98304) {
        int u  = t - 65536;
        int l  = u >> 12;
        int ch = (u >> 10) & 3;
        int w  = u & 1023;
        int np = w >> 7, ktl = (w >> 5) & 3, lane = w & 31;
        int nE = np*16 + (lane >> 2);
        int nO = nE + 8;
        int k0 = ch*64 + ktl*16 + (lane & 3)*2;
        float v[8];
        #pragma unroll
        for (int q = 0; q < 4; q++) {
            int n = (q < 2) ? nE : nO;
            int kk = k0 + ((q & 1) ? 8 : 0);
            v[q*2]   = W2[l*32768 + kk*128 + n];
            v[q*2+1] = W2[l*32768 + (kk+1)*128 + n];
        }
        uint4 F;
        F.x = cvt2h(v[0], v[1]);
        F.y = cvt2h(v[2], v[3]);
        F.z = cvt2h(v[4], v[5]);
        F.w = cvt2h(v[6], v[7]);
        g_w2img[(size_t)(l*4 + ch)*1024 + w] = F;
    }
}

// ---------------- k_s: 320-edge halves, 16-ch slices, 3 CTA/SM, fp16 out ----------------
#define XS_STRIDE 20
#define XS_F (ATOMS*KH*XS_STRIDE)   /* 12160 */
#define YS_E 320
#define YS_F (YS_E*KH)              /* 6080 */
__global__ __launch_bounds__(256, 3) void k_s(const int* __restrict__ ei) {
    int cq = blockIdx.x;          // 0..7 (16-channel slice)
    int eh = blockIdx.y;          // 0..1 (320-edge half)
    int cb = blockIdx.z;
    int tid = threadIdx.x;
    extern __shared__ float sm[];
    float* xs  = sm;                      // [atom][k] stride 20
    float* Ys  = sm + XS_F;               // [320][19]
    int*  srcs = (int*)(Ys + YS_F);
    int abase = cb*ATOMS;
    int c0 = cq*16;
    int gebase = cb*640 + eh*320;
    for (int i = tid; i < ATOMS*KH*16; i += 256) {
        int a = i/(KH*16); int r = i - a*(KH*16); int k = r >> 4; int c = r & 15;
        xs[(a*KH + k)*XS_STRIDE + c] = g_x[((size_t)(abase+a)*KH + k)*CCH + c0 + c];
    }
    for (int i = tid; i < YS_F; i += 256) Ys[i] = g_Y[(size_t)gebase*KH + i];
    for (int i = tid; i < YS_E; i += 256) srcs[i] = ei[gebase + i] - abase;
    __syncthreads();
    int cg = tid & 3, er = tid >> 2;      // 4 channel-groups x 64 edge rows
    #pragma unroll
    for (int j = 0; j < 5; j++) {
        int e = j*64 + er;
        int sl = srcs[e];
        const float* xr = &xs[sl*(KH*XS_STRIDE) + cg*4];
        const float* yr = &Ys[e*KH];
        float4 acc = make_float4(0.f, 0.f, 0.f, 0.f);
        #pragma unroll
        for (int k = 0; k < KH; k++) {
            float y = yr[k];
            float4 xv = *(const float4*)&xr[k*XS_STRIDE];
            acc.x = fmaf(y, xv.x, acc.x);
            acc.y = fmaf(y, xv.y, acc.y);
            acc.z = fmaf(y, xv.z, acc.z);
            acc.w = fmaf(y, xv.w, acc.w);
        }
        uint2 st;
        st.x = cvt2h(acc.x, acc.y);
        st.y = cvt2h(acc.z, acc.w);
        *(uint2*)&g_s[(size_t)(gebase+e)*CCH + c0 + cg*4] = st;
    }
}

// ---------------- k_mlp: fp16 single-pass, 1024 thr, fused agg ----------------
#define SM_MLP   206336

__global__ __launch_bounds__(1024, 1) void k_mlp(int layer) {
    extern __shared__ char smem[];
    int tid = threadIdx.x;
    int wid = tid >> 5, lane = tid & 31;
    int mw = wid & 3, nw = wid >> 2;       // 4 m-warps x 8 n-warps
    int cta = blockIdx.x;
    int e0 = cta * 128;
    int g  = lane >> 2;
    int tg = lane & 3;

    uint4* sA0 = (uint4*)smem;             // 16 KB
    uint4* sA1 = (uint4*)(smem + 16384);   // 16 KB
    uint4* Bb0 = (uint4*)(smem + 65536);   // 32 KB
    uint4* Bb1 = (uint4*)(smem + 98304);   // 32 KB
    uint4* hs4 = (uint4*)smem;             // 64 KB h img after GEMM1
    u32*   hsw = (u32*)smem;

    int nh  = nw >> 2;          // 0..1
    int np2 = (nw & 3) * 2;     // n16-pair base

    // ---- hoist s fragment LDGs (fp16 pairs, pre-converted) ----
    u32 sv[2][4];
    {
        const u32* gs32 = (const u32*)g_s;
        int w = tid;
        int mt = w >> 7, ktl = (w >> 5) & 3, ln = w & 31;
        int m0 = mt*16 + (ln >> 2);
        int kkb = ktl*16 + (ln & 3)*2;
        size_t row0 = (size_t)(e0 + m0)*CCH;
        size_t row1 = row0 + 8*CCH;
        #pragma unroll
        for (int ch = 0; ch < 2; ch++) {
            int kk = ch*64 + kkb;
            sv[ch][0] = gs32[(row0 + kk) >> 1];
            sv[ch][1] = gs32[(row1 + kk) >> 1];
            sv[ch][2] = gs32[(row0 + kk + 8) >> 1];
            sv[ch][3] = gs32[(row1 + kk + 8) >> 1];
        }
    }

    #define FILL_B1(ch, Bp)                                                          \
    {                                                                                \
        const uint4* b0 = g_w1img + (size_t)((layer*2 + 0)*4 + (ch))*1024;           \
        const uint4* b1 = g_w1img + (size_t)((layer*2 + 1)*4 + (ch))*1024;           \
        cpasync16(&(Bp)[tid],        &b0[tid]);                                      \
        cpasync16(&(Bp)[1024 + tid], &b1[tid]);                                      \
    }
    #define FILL_A(ch, Ap)                                                           \
    {                                                                                \
        const uint4* gA = g_aimg + (size_t)(cta*4 + (ch))*1024;                      \
        cpasync16(&(Ap)[tid], &gA[tid]);                                             \
    }

    FILL_B1(0, Bb0); CP_COMMIT;   // g1
    sA0[tid] = make_uint4(sv[0][0], sv[0][1], sv[0][2], sv[0][3]);
    sA1[tid] = make_uint4(sv[1][0], sv[1][1], sv[1][2], sv[1][3]);
    FILL_B1(1, Bb1); CP_COMMIT;   // g2

    float acc1[2][4][4];
    #pragma unroll
    for (int s = 0; s < 2; s++)
        #pragma unroll
        for (int j = 0; j < 4; j++)
            #pragma unroll
            for (int q = 0; q < 4; q++) acc1[s][j][q] = 0.f;

    #define G1_COMPUTE(Acur, Bcur)                                               \
    {                                                                            \
        _Pragma("unroll")                                                        \
        for (int kt = 0; kt < 4; kt++) {                                         \
            uint4 aF[2];                                                         \
            _Pragma("unroll")                                                    \
            for (int s = 0; s < 2; s++)                                          \
                aF[s] = (Acur)[((mw*2 + s)*4 + kt)*32 + lane];                   \
            _Pragma("unroll")                                                    \
            for (int j = 0; j < 2; j++) {                                        \
                uint4 bF = (Bcur)[nh*1024 + ((np2 + j)*4 + kt)*32 + lane];       \
                _Pragma("unroll")                                                \
                for (int s = 0; s < 2; s++) {                                    \
                    mma16816h(acc1[s][2*j],   aF[s], bF.x, bF.y);                \
                    mma16816h(acc1[s][2*j+1], aF[s], bF.z, bF.w);                \
                }                                                                \
            }                                                                    \
        }                                                                        \
    }

    CP_WAIT1; __syncthreads();          // B(0) ready
    G1_COMPUTE(sA0, Bb0);               // ch 0
    __syncthreads();
    FILL_A(2, sA0); FILL_B1(2, Bb0); CP_COMMIT;   // g3
    CP_WAIT1; __syncthreads();          // B(1) ready
    G1_COMPUTE(sA1, Bb1);               // ch 1
    __syncthreads();
    FILL_A(3, sA1); FILL_B1(3, Bb1); CP_COMMIT;   // g4
    CP_WAIT1; __syncthreads();          // A(2)/B(2) ready
    G1_COMPUTE(sA0, Bb0);               // ch 2
    __syncthreads();
    {   // prefetch GEMM2 B(0) into Bb0 front
        const uint4* gB = g_w2img + (size_t)(layer*4 + 0)*1024;
        cpasync16(&Bb0[tid], &gB[tid]);
        CP_COMMIT;   // g5
    }
    CP_WAIT1; __syncthreads();          // A(3)/B(3) ready
    G1_COMPUTE(sA1, Bb1);               // ch 3
    __syncthreads();                    // sA region free -> h storage

    // ---- epilogue 1: silu -> fp16 h fragments ----
    #pragma unroll
    for (int s = 0; s < 2; s++)
        #pragma unroll
        for (int nt = 0; nt < 4; nt++) {
            float c0 = acc1[s][nt][0], c1 = acc1[s][nt][1];
            float c2 = acc1[s][nt][2], c3 = acc1[s][nt][3];
            c0 = c0 / (1.f + __expf(-c0));
            c1 = c1 / (1.f + __expf(-c1));
            c2 = c2 / (1.f + __expf(-c2));
            c3 = c3 / (1.f + __expf(-c3));
            int C = nh*128 + (np2 + (nt >> 1))*16 + (nt & 1)*8 + tg*2;
            u32 w01 = cvt2h(c0, c1);
            u32 w23 = cvt2h(c2, c3);
            int mtp  = mw*2 + s;
            int ktp  = C >> 4;
            int khal = (C >> 3) & 1;
            int lanep = g*4 + tg;
            u32 base = (((u32)(mtp*16 + ktp)*32 + lanep) << 2);
            hsw[base + 2*khal]     = w01;
            hsw[base + 2*khal + 1] = w23;
        }
    CP_WAIT0;
    __syncthreads();

    // ===================== GEMM2 (B ping/pong 16KB @65536/81920) =====================
    float acc2[2][2][4];
    #pragma unroll
    for (int s = 0; s < 2; s++)
        #pragma unroll
        for (int j = 0; j < 2; j++)
            #pragma unroll
            for (int q = 0; q < 4; q++) acc2[s][j][q] = 0.f;

    for (int ch = 0; ch < 4; ch++) {
        if (ch < 3) {
            const uint4* gB = g_w2img + (size_t)(layer*4 + ch + 1)*1024;
            uint4* Bnx = (uint4*)(smem + 65536 + (((ch+1) & 1) ? 16384 : 0));
            cpasync16(&Bnx[tid], &gB[tid]);
            CP_COMMIT;
        }
        const uint4* Bcur = (const uint4*)(smem + 65536 + ((ch & 1) ? 16384 : 0));
        #pragma unroll
        for (int kt = 0; kt < 4; kt++) {
            int ktg = ch*4 + kt;
            uint4 aF[2];
            #pragma unroll
            for (int s = 0; s < 2; s++)
                aF[s] = hs4[((mw*2 + s)*16 + ktg)*32 + lane];
            uint4 bF = Bcur[(nw*4 + kt)*32 + lane];
            #pragma unroll
            for (int s = 0; s < 2; s++) {
                mma16816h(acc2[s][0], aF[s], bF.x, bF.y);
                mma16816h(acc2[s][1], aF[s], bF.z, bF.w);
            }
        }
        if (ch < 3) { CP_WAIT0; __syncthreads(); }
    }
    __syncthreads();

    // ---- Y tile cp.async + m epilogue ----
    {
        const uint4* gY = (const uint4*)(g_Y + (size_t)e0*KH);
        uint4* yd = (uint4*)(smem + 196608);
        if (tid < 608) cpasync16(&yd[tid], &gY[tid]);
        CP_COMMIT;
    }
    float* mSf = (float*)(smem + 131072);
    #pragma unroll
    for (int s = 0; s < 2; s++)
        #pragma unroll
        for (int j = 0; j < 2; j++) {
            int R = mw*32 + s*16 + g;
            int C = nw*16 + j*8 + tg*2;
            mSf[R*128 + C]       = acc2[s][j][0];
            mSf[R*128 + C + 1]   = acc2[s][j][1];
            mSf[(R+8)*128 + C]   = acc2[s][j][2];
            mSf[(R+8)*128 + C+1] = acc2[s][j][3];
        }
    CP_WAIT0;
    __syncthreads();

    // ---- fused aggregation ----
    {
        const float* Ysf = (const float*)(smem + 196608);
        int al = tid >> 7, c = tid & 127;
        int aStart = e0 / 20;
        int n = aStart + al;
        int lo = n*20 - e0;        if (lo < 0) lo = 0;
        int hi = n*20 + 19 - e0;   if (hi > 127) hi = 127;
        if (lo <= hi) {
            float acc[KH];
            #pragma unroll
            for (int k = 0; k < KH; k++) acc[k] = 0.f;
            for (int e = lo; e <= hi; e++) {
                float mv = mSf[e*128 + c];
                #pragma unroll
                for (int k = 0; k < KH; k++) acc[k] = fmaf(Ysf[e*KH + k], mv, acc[k]);
            }
            #pragma unroll
            for (int k = 0; k < KH; k++)
                atomicAdd(&g_x[((size_t)n*KH + k)*CCH + c], 0.05f*acc[k]);
        }
    }
}

// ---------------- k_hw ----------------
__global__ void k_hw(const float* __restrict__ wf) {
    int n = blockIdx.x, lane = threadIdx.x;
    float v = 0.f;
    for (int c = lane; c < CCH; c += 32) v += g_x[(size_t)n*(KH*CCH) + c]*wf[c];
    #pragma unroll
    for (int off = 16; off; off >>= 1) v += __shfl_xor_sync(0xffffffffu, v, off);
    if (lane == 0) g_hw[n] = v;
}

// ---------------- k_out ----------------
__global__ void k_out(const float* __restrict__ Wa, const float* __restrict__ ba,
                      const int* __restrict__ ei, float* __restrict__ out) {
    int n = blockIdx.x, tid = threadIdx.x;
    __shared__ float hs[CCH];
    hs[tid] = g_x[(size_t)n*(KH*CCH) + tid];
    __syncthreads();
    if (tid < 100) {
        float acc = ba[tid];
        for (int c = 0; c < CCH; c++) acc = fmaf(hs[c], Wa[c*100 + tid], acc);
        out[NATOM*3 + n*100 + tid] = acc;
    } else if (tid < 103) {
        int j = tid - 100;
        float hwn = g_hw[n];
        float acc = 0.f;
        for (int e = 0; e < NBR; e++) {
            int ge = n*NBR + e;
            acc = fmaf(g_hw[ei[ge]] - hwn, g_dirn[ge*3 + j], acc);
        }
        out[n*3 + j] = acc;
    }
}

// ---------------- launch ----------------
static const int SMEM_S = (XS_F + YS_F + YS_E) * 4;   // 74240 B -> 3 CTA/SM

extern "C" void kernel_launch(void* const* d_in, const int* in_sizes, int n_in,
                              void* d_out, int out_size) {
    const float* z       = (const float*)d_in[0];
    const float* frac    = (const float*)d_in[1];
    const int*   types   = (const int*)  d_in[2];
    const float* lengths = (const float*)d_in[4];
    const float* angles  = (const float*)d_in[5];
    const int*   ei      = (const int*)  d_in[7];
    const float* emb     = (const float*)d_in[8];
    const float* zproj   = (const float*)d_in[9];
    const float* Wd      = (const float*)d_in[10];
    const float* W1      = (const float*)d_in[11];
    const float* W2      = (const float*)d_in[12];
    const float* Wa      = (const float*)d_in[13];
    const float* ba      = (const float*)d_in[14];
    const float* wf      = (const float*)d_in[15];
    float* out = (float*)d_out;

    cudaFuncSetAttribute(k_s,   cudaFuncAttributeMaxDynamicSharedMemorySize, SMEM_S);
    cudaFuncSetAttribute(k_mlp, cudaFuncAttributeMaxDynamicSharedMemorySize, SM_MLP);

    k_init <<<NCRYST, 512>>>(z, frac, lengths, angles, zproj, types, emb, ei);
    k_wconv<<<384, 256>>>(W1, Wd, W2);
    for (int l = 0; l < NLAYER; l++) {
        k_s  <<<dim3(8, 2, NCRYST), 256, SMEM_S>>>(ei);
        k_mlp<<<NCTA_MLP, 1024, SM_MLP>>>(l);
    }
    k_hw <<<NATOM, 32>>>(wf);
    k_out<<<NATOM, 128>>>(Wa, ba, ei, out);
}